// round 5
// baseline (speedup 1.0000x reference)
#include <cuda_runtime.h>

typedef unsigned long long ull;

// GMM EM on GB300. B=8, N=80000, K=5, F=20, 5 iterations + final E-step.
// Inputs:  d_in[0]=data [B,N,F], d_in[1]=means [B,K,F], d_in[2]=variance [B,K,F], d_in[3]=prior [B,K]
// Output:  concat( ll [B,N,K], post [B,N,K], means [B,K,F], var [B,K,F], pi [B,K] ) fp32

#define Bn 8
#define Nn 80000
#define Kn 5
#define Fn 20
#define NITER 5
#define TILE 512                           // points per tile (2 per thread)
#define NTILES ((Nn + TILE - 1) / TILE)    // 157 (last tile: 128 valid)
#define GRIDX 37                           // 37*8 = 296 blocks = one wave at occ 2
#define TO 256                             // estep_out tile
#define NTO ((Nn + TO - 1) / TO)           // 313

// Per-(b): Sx[k][f] at k*21+f (f==20 is the constant-1 feature -> Sx == cluster size S),
//          Sxx[k][f] at 105 + k*21+f.
__device__ float g_acc[Bn * 210];

// Per-(b,k) E-step params, 44 floats (11 float4):
// float4 j (j=0..9): {A_{2j}, A_{2j+1}, B_{2j}, B_{2j+1}} with A_f = -0.5/(var+eps), B_f = mu/(var+eps)
// [40] = C = log(pi) - 0.5*sum log(2pi var) - 0.5*sum mu^2/(var+eps)
__device__ float4 g_params4[Bn * Kn * 11];

// ---------------------------------------------------------------- f32x2 helpers
__device__ __forceinline__ ull pk2(float lo, float hi) {
    ull r; asm("mov.b64 %0,{%1,%2};" : "=l"(r) : "f"(lo), "f"(hi)); return r;
}
__device__ __forceinline__ void up2(ull v, float& lo, float& hi) {
    asm("mov.b64 {%0,%1},%2;" : "=f"(lo), "=f"(hi) : "l"(v));
}
__device__ __forceinline__ ull fma2(ull a, ull b, ull c) {
    ull d; asm("fma.rn.f32x2 %0,%1,%2,%3;" : "=l"(d) : "l"(a), "l"(b), "l"(c)); return d;
}
__device__ __forceinline__ ull mul2(ull a, ull b) {
    ull d; asm("mul.rn.f32x2 %0,%1,%2;" : "=l"(d) : "l"(a), "l"(b)); return d;
}

// ---------------------------------------------------------------- params writer
__device__ __forceinline__ void write_params(int b, int k, float C_base,
                                             const float* mu, const float* var) {
    float* gp = reinterpret_cast<float*>(g_params4) + (b * Kn + k) * 44;
    float C = C_base;
    float A[Fn], Bc[Fn];
#pragma unroll
    for (int f = 0; f < Fn; f++) {
        float v = var[f];
        float m = mu[f];
        float ic = 1.0f / (v + 1e-6f);
        C += -0.5f * logf(6.283185307179586f * v) - 0.5f * ic * m * m;
        A[f]  = -0.5f * ic;
        Bc[f] = ic * m;
    }
#pragma unroll
    for (int j = 0; j < 10; j++) {
        gp[4 * j]     = A[2 * j];
        gp[4 * j + 1] = A[2 * j + 1];
        gp[4 * j + 2] = Bc[2 * j];
        gp[4 * j + 3] = Bc[2 * j + 1];
    }
    gp[40] = C;
}

// ---------------------------------------------------------------- init
__global__ void init_kernel(const float* __restrict__ means,
                            const float* __restrict__ var,
                            const float* __restrict__ pri) {
    int tid = threadIdx.x;
    if (tid < Bn * Kn) {
        int b = tid / Kn, k = tid - b * Kn;
        float mu[Fn], vv[Fn];
#pragma unroll
        for (int f = 0; f < Fn; f++) {
            mu[f] = means[(b * Kn + k) * Fn + f];
            vv[f] = var[(b * Kn + k) * Fn + f];
        }
        write_params(b, k, logf(pri[b * Kn + k]), mu, vv);
    }
    for (int i = tid; i < Bn * 210; i += blockDim.x) g_acc[i] = 0.0f;
}

// ---------------------------------------------------------------- E-step core
struct EStepSmem {
    ulonglong2 AB[Kn][10];   // .x = packed(A_{2j},A_{2j+1}), .y = packed(B_{2j},B_{2j+1})
    float      C[Kn];
};

__device__ __forceinline__ void load_params_smem(EStepSmem* sp, int b, int tid) {
    if (tid < Kn * 11) {
        int k = tid / 11, q = tid - k * 11;
        float4 v = g_params4[(b * Kn + k) * 11 + q];
        if (q < 10) {
            ulonglong2 w;
            w.x = pk2(v.x, v.y);
            w.y = pk2(v.z, v.w);
            sp->AB[k][q] = w;
        } else {
            sp->C[k] = v.x;
        }
    }
}

__device__ __forceinline__ void loadx(const float* __restrict__ src, ull* x2) {
    const ulonglong2* xp = reinterpret_cast<const ulonglong2*>(src);
#pragma unroll
    for (int j = 0; j < 5; j++) {
        ulonglong2 v = __ldg(xp + j);
        x2[2 * j]     = v.x;
        x2[2 * j + 1] = v.y;
    }
}

__device__ __forceinline__ void softmax5(const float* l, float* p) {
    float m = l[0];
#pragma unroll
    for (int k = 1; k < Kn; k++) m = fmaxf(m, l[k]);
    float s = 0.0f;
#pragma unroll
    for (int k = 0; k < Kn; k++) { p[k] = __expf(l[k] - m); s += p[k]; }
    float inv = __fdividef(1.0f, s);
#pragma unroll
    for (int k = 0; k < Kn; k++) p[k] *= inv;
}

__device__ __forceinline__ void loglik_softmax(const EStepSmem* sp, const ull* x2,
                                               float* l, float* p) {
#pragma unroll
    for (int k = 0; k < Kn; k++) {
        ull acc = 0ULL;
#pragma unroll
        for (int j = 0; j < 10; j++) {
            ulonglong2 ab = sp->AB[k][j];
            acc = fma2(fma2(ab.x, x2[j], ab.y), x2[j], acc);  // x*(A*x+B) per lane
        }
        float lo, hi; up2(acc, lo, hi);
        l[k] = sp->C[k] + lo + hi;
    }
    softmax5(l, p);
}

// ---------------------------------------------------------------- accumulate (E-step + partial M-step sums)
__launch_bounds__(256, 2)
__global__ void accum_kernel(const float* __restrict__ data) {
    __shared__ EStepSmem sp;
    __shared__ __align__(16) float sP[Kn][TILE];   // posteriors transposed [k][t]
    __shared__ float sred[8 * 210];

    const int tid  = threadIdx.x;
    const int b    = blockIdx.y;
    const int wid  = tid >> 5;
    const int lane = tid & 31;

    load_params_smem(&sp, b, tid);

    ull Sx2[Kn]  = {0, 0, 0, 0, 0};   // f32x2 lane-paired accumulators
    ull Sxx2[Kn] = {0, 0, 0, 0, 0};
    const ull ONE2 = pk2(1.0f, 1.0f);
    const float* dbase = data + (size_t)b * Nn * Fn;

    for (int tile = blockIdx.x; tile < NTILES; tile += GRIDX) {
        const int base   = tile * TILE;
        const int nvalid = min(TILE, Nn - base);

        __syncthreads();   // sP safe to overwrite

        // -------- phase 1: each thread handles points (base+tid) and (base+tid+256)
        if (nvalid == TILE) {
            ull xa[10], xb[10];
            loadx(dbase + (size_t)(base + tid) * Fn, xa);
            loadx(dbase + (size_t)(base + tid + 256) * Fn, xb);
            float la[Kn], lb[Kn];
#pragma unroll
            for (int k = 0; k < Kn; k++) {
                ull acca = 0ULL, accb = 0ULL;
#pragma unroll
                for (int j = 0; j < 10; j++) {
                    ulonglong2 ab = sp.AB[k][j];   // one LDS.128, two uses
                    acca = fma2(fma2(ab.x, xa[j], ab.y), xa[j], acca);
                    accb = fma2(fma2(ab.x, xb[j], ab.y), xb[j], accb);
                }
                float lo, hi;
                up2(acca, lo, hi); la[k] = sp.C[k] + lo + hi;
                up2(accb, lo, hi); lb[k] = sp.C[k] + lo + hi;
            }
            float pa[Kn], pb[Kn];
            softmax5(la, pa);
            softmax5(lb, pb);
#pragma unroll
            for (int k = 0; k < Kn; k++) sP[k][tid]       = pa[k];
#pragma unroll
            for (int k = 0; k < Kn; k++) sP[k][tid + 256] = pb[k];
        } else {
            // tail tile (only one per b): per-point fallback
            if (tid < nvalid) {
                ull x2[10];
                loadx(dbase + (size_t)(base + tid) * Fn, x2);
                float l[Kn], p[Kn];
                loglik_softmax(&sp, x2, l, p);
#pragma unroll
                for (int k = 0; k < Kn; k++) sP[k][tid] = p[k];
            }
            if (tid + 256 < nvalid) {
                ull x2[10];
                loadx(dbase + (size_t)(base + tid + 256) * Fn, x2);
                float l[Kn], p[Kn];
                loglik_softmax(&sp, x2, l, p);
#pragma unroll
                for (int k = 0; k < Kn; k++) sP[k][tid + 256] = p[k];
            }
        }
        __syncthreads();

        // -------- phase 2: warp owns 64 points (2 at a time via f32x2), lane owns feature f
        const int t0w = wid * 64;
        int rem = nvalid - t0w;
        int cnt = rem < 0 ? 0 : (rem > 64 ? 64 : rem);
        const bool act = lane < 20;
        const float* xr = dbase + (size_t)(base + t0w) * Fn + (act ? lane : 0);

        if (cnt == 64) {
#pragma unroll 8
            for (int i = 0; i < 64; i += 2) {
                float xa = xr[i * Fn];            // L1 hit (loaded by phase 1)
                float xb = xr[i * Fn + Fn];
                ull x2p = act ? pk2(xa, xb) : ONE2;
                ull xx2 = mul2(x2p, x2p);
#pragma unroll
                for (int k = 0; k < Kn; k++) {
                    ull p2 = *reinterpret_cast<const ull*>(&sP[k][t0w + i]);  // broadcast LDS.64
                    Sx2[k]  = fma2(p2, x2p, Sx2[k]);
                    Sxx2[k] = fma2(p2, xx2, Sxx2[k]);
                }
            }
        } else if (cnt > 0) {
            int i = 0;
            for (; i + 1 < cnt; i += 2) {
                float xa = xr[i * Fn];
                float xb = xr[i * Fn + Fn];
                ull x2p = act ? pk2(xa, xb) : ONE2;
                ull xx2 = mul2(x2p, x2p);
#pragma unroll
                for (int k = 0; k < Kn; k++) {
                    ull p2 = *reinterpret_cast<const ull*>(&sP[k][t0w + i]);
                    Sx2[k]  = fma2(p2, x2p, Sx2[k]);
                    Sxx2[k] = fma2(p2, xx2, Sxx2[k]);
                }
            }
            if (i < cnt) {   // odd tail
                float xa = xr[i * Fn];
                ull x2p = act ? pk2(xa, 0.0f) : pk2(1.0f, 0.0f);
                ull xx2 = mul2(x2p, x2p);
#pragma unroll
                for (int k = 0; k < Kn; k++) {
                    ull p2 = pk2(sP[k][t0w + i], 0.0f);
                    Sx2[k]  = fma2(p2, x2p, Sx2[k]);
                    Sxx2[k] = fma2(p2, xx2, Sxx2[k]);
                }
            }
        }
    }

    // -------- block reduction + one atomicAdd per entry
    __syncthreads();
    if (lane < 21) {   // lane 20 carries the Sigma-p (ones-feature) column
#pragma unroll
        for (int k = 0; k < Kn; k++) {
            float lo, hi; up2(Sx2[k], lo, hi);
            sred[wid * 210 + k * 21 + lane] = lo + hi;
        }
#pragma unroll
        for (int k = 0; k < Kn; k++) {
            float lo, hi; up2(Sxx2[k], lo, hi);
            sred[wid * 210 + 105 + k * 21 + lane] = lo + hi;
        }
    }
    __syncthreads();
    if (tid < 210) {
        float v = 0.0f;
#pragma unroll
        for (int w = 0; w < 8; w++) v += sred[w * 210 + tid];
        atomicAdd(&g_acc[b * 210 + tid], v);
    }
}

// ---------------------------------------------------------------- M-step finalize (+ param refresh, + output on last iter)
__global__ void finalize_kernel(int is_last, float* __restrict__ out_means,
                                float* __restrict__ out_var, float* __restrict__ out_pi) {
    int tid = threadIdx.x;
    __shared__ float sS[Bn * Kn];
    if (tid < Bn * Kn) {
        int b = tid / Kn, k = tid - b * Kn;
        sS[tid] = g_acc[b * 210 + k * 21 + 20];
    }
    __syncthreads();
    if (tid < Bn * Kn) {
        int b = tid / Kn, k = tid - b * Kn;
        float S = sS[tid];
        float sum = sS[b * Kn + 0] + sS[b * Kn + 1] + sS[b * Kn + 2] +
                    sS[b * Kn + 3] + sS[b * Kn + 4];
        // pi = (S/N) / max(sum|S|/N, 1e-12) == S / max(sum, N*1e-12)
        float pi = S / fmaxf(sum, (float)Nn * 1e-12f);
        float dS = S + 1e-7f;
        float invdS = 1.0f / dS;

        float mu[Fn], vv[Fn];
#pragma unroll
        for (int f = 0; f < Fn; f++) {
            float sx  = g_acc[b * 210 + k * 21 + f];
            float sxx = g_acc[b * 210 + 105 + k * 21 + f];
            float m = sx * invdS;
            float v = (sxx - 2.0f * m * sx + m * m * S) * invdS + 1e-6f;  // var + EPS_VAR
            mu[f] = m;
            vv[f] = v;
        }
        write_params(b, k, logf(pi), mu, vv);
        if (is_last) {
#pragma unroll
            for (int f = 0; f < Fn; f++) {
                out_means[(b * Kn + k) * Fn + f] = mu[f];
                out_var[(b * Kn + k) * Fn + f]   = vv[f];
            }
            out_pi[b * Kn + k] = pi;
        }
    }
    __syncthreads();
    for (int i = tid; i < Bn * 210; i += blockDim.x) g_acc[i] = 0.0f;
}

// ---------------------------------------------------------------- final E-step: write ll + post [B,N,K]
__launch_bounds__(TO)
__global__ void estep_out_kernel(const float* __restrict__ data,
                                 float* __restrict__ out_ll,
                                 float* __restrict__ out_post) {
    __shared__ EStepSmem sp;
    const int tid = threadIdx.x;
    const int b   = blockIdx.y;
    load_params_smem(&sp, b, tid);
    __syncthreads();

    int n = blockIdx.x * TO + tid;
    if (n < Nn) {
        ull x2[10];
        loadx(data + ((size_t)b * Nn + n) * Fn, x2);
        float l[Kn], p[Kn];
        loglik_softmax(&sp, x2, l, p);

        size_t o = ((size_t)b * Nn + n) * Kn;
#pragma unroll
        for (int k = 0; k < Kn; k++) out_ll[o + k] = l[k];
#pragma unroll
        for (int k = 0; k < Kn; k++) out_post[o + k] = p[k];
    }
}

// ---------------------------------------------------------------- launch
extern "C" void kernel_launch(void* const* d_in, const int* in_sizes, int n_in,
                              void* d_out, int out_size) {
    const float* data  = (const float*)d_in[0];
    const float* means = (const float*)d_in[1];
    const float* var   = (const float*)d_in[2];
    const float* pri   = (const float*)d_in[3];

    float* out = (float*)d_out;
    size_t NK = (size_t)Bn * Nn * Kn;                 // 3,200,000
    float* out_ll    = out;
    float* out_post  = out + NK;
    float* out_means = out + 2 * NK;
    float* out_var   = out_means + Bn * Kn * Fn;      // +800
    float* out_pi    = out_var   + Bn * Kn * Fn;      // +800

    init_kernel<<<1, 256>>>(means, var, pri);
    for (int it = 0; it < NITER; it++) {
        accum_kernel<<<dim3(GRIDX, Bn), 256>>>(data);
        finalize_kernel<<<1, 256>>>(it == NITER - 1 ? 1 : 0, out_means, out_var, out_pi);
    }
    estep_out_kernel<<<dim3(NTO, Bn), TO>>>(data, out_ll, out_post);
}

// round 7
// speedup vs baseline: 1.1557x; 1.1557x over previous
#include <cuda_runtime.h>

typedef unsigned long long ull;

// GMM EM on GB300. B=8, N=80000, K=5, F=20, 5 iterations + final E-step.
// Inputs:  d_in[0]=data [B,N,F], d_in[1]=means [B,K,F], d_in[2]=variance [B,K,F], d_in[3]=prior [B,K]
// Output:  concat( ll [B,N,K], post [B,N,K], means [B,K,F], var [B,K,F], pi [B,K] ) fp32

#define Bn 8
#define Nn 80000
#define Kn 5
#define Fn 20
#define NITER 5
#define TILE 512                           // points per tile (2 per thread)
#define NTILES ((Nn + TILE - 1) / TILE)    // 157 (last tile: 128 valid)
#define GRIDX 53                           // 53*8 = 424 blocks ~ one wave at 3 blocks/SM
#define TO 256                             // estep_out tile
#define NTO ((Nn + TO - 1) / TO)           // 313

// Per-(b): Sx[k][f] at k*21+f (f==20 is the constant-1 feature -> Sx == cluster size S),
//          Sxx[k][f] at 105 + k*21+f.
__device__ float g_acc[Bn * 210];

// Per-(b,k) E-step params, 44 floats (11 float4):
// float4 j (j=0..9): {A_{2j}, A_{2j+1}, B_{2j}, B_{2j+1}} with A_f = -0.5/(var+eps), B_f = mu/(var+eps)
// [40] = C = log(pi) - 0.5*sum log(2pi var) - 0.5*sum mu^2/(var+eps)
__device__ float4 g_params4[Bn * Kn * 11];

// ---------------------------------------------------------------- f32x2 helpers
__device__ __forceinline__ ull pk2(float lo, float hi) {
    ull r; asm("mov.b64 %0,{%1,%2};" : "=l"(r) : "f"(lo), "f"(hi)); return r;
}
__device__ __forceinline__ void up2(ull v, float& lo, float& hi) {
    asm("mov.b64 {%0,%1},%2;" : "=f"(lo), "=f"(hi) : "l"(v));
}
__device__ __forceinline__ ull fma2(ull a, ull b, ull c) {
    ull d; asm("fma.rn.f32x2 %0,%1,%2,%3;" : "=l"(d) : "l"(a), "l"(b), "l"(c)); return d;
}
__device__ __forceinline__ ull mul2(ull a, ull b) {
    ull d; asm("mul.rn.f32x2 %0,%1,%2;" : "=l"(d) : "l"(a), "l"(b)); return d;
}

// ---------------------------------------------------------------- params writer
__device__ __forceinline__ void write_params(int b, int k, float C_base,
                                             const float* mu, const float* var) {
    float* gp = reinterpret_cast<float*>(g_params4) + (b * Kn + k) * 44;
    float C = C_base;
    float A[Fn], Bc[Fn];
#pragma unroll
    for (int f = 0; f < Fn; f++) {
        float v = var[f];
        float m = mu[f];
        float ic = 1.0f / (v + 1e-6f);
        C += -0.5f * logf(6.283185307179586f * v) - 0.5f * ic * m * m;
        A[f]  = -0.5f * ic;
        Bc[f] = ic * m;
    }
#pragma unroll
    for (int j = 0; j < 10; j++) {
        gp[4 * j]     = A[2 * j];
        gp[4 * j + 1] = A[2 * j + 1];
        gp[4 * j + 2] = Bc[2 * j];
        gp[4 * j + 3] = Bc[2 * j + 1];
    }
    gp[40] = C;
}

// ---------------------------------------------------------------- init
__global__ void init_kernel(const float* __restrict__ means,
                            const float* __restrict__ var,
                            const float* __restrict__ pri) {
    int tid = threadIdx.x;
    if (tid < Bn * Kn) {
        int b = tid / Kn, k = tid - b * Kn;
        float mu[Fn], vv[Fn];
#pragma unroll
        for (int f = 0; f < Fn; f++) {
            mu[f] = means[(b * Kn + k) * Fn + f];
            vv[f] = var[(b * Kn + k) * Fn + f];
        }
        write_params(b, k, logf(pri[b * Kn + k]), mu, vv);
    }
    for (int i = tid; i < Bn * 210; i += blockDim.x) g_acc[i] = 0.0f;
}

// ---------------------------------------------------------------- E-step core
struct EStepSmem {
    ulonglong2 AB[Kn][10];   // .x = packed(A_{2j},A_{2j+1}), .y = packed(B_{2j},B_{2j+1})
    float      C[Kn];
};

__device__ __forceinline__ void load_params_smem(EStepSmem* sp, int b, int tid) {
    if (tid < Kn * 11) {
        int k = tid / 11, q = tid - k * 11;
        float4 v = g_params4[(b * Kn + k) * 11 + q];
        if (q < 10) {
            ulonglong2 w;
            w.x = pk2(v.x, v.y);
            w.y = pk2(v.z, v.w);
            sp->AB[k][q] = w;
        } else {
            sp->C[k] = v.x;
        }
    }
}

__device__ __forceinline__ void softmax5(const float* l, float* p) {
    float m = l[0];
#pragma unroll
    for (int k = 1; k < Kn; k++) m = fmaxf(m, l[k]);
    float s = 0.0f;
#pragma unroll
    for (int k = 0; k < Kn; k++) { p[k] = __expf(l[k] - m); s += p[k]; }
    float inv = __fdividef(1.0f, s);
#pragma unroll
    for (int k = 0; k < Kn; k++) p[k] *= inv;
}

// single-point log-lik + softmax (tail path / estep_out)
__device__ __forceinline__ void loglik_softmax1(const EStepSmem* sp,
                                                const float* __restrict__ src,
                                                float* l, float* p) {
    const ulonglong2* xp = reinterpret_cast<const ulonglong2*>(src);
    ull acc[Kn] = {0, 0, 0, 0, 0};
#pragma unroll
    for (int jj = 0; jj < 5; jj++) {
        ulonglong2 v = __ldg(xp + jj);
#pragma unroll
        for (int k = 0; k < Kn; k++) {
            ulonglong2 ab0 = sp->AB[k][2 * jj];
            ulonglong2 ab1 = sp->AB[k][2 * jj + 1];
            acc[k] = fma2(fma2(ab0.x, v.x, ab0.y), v.x, acc[k]);
            acc[k] = fma2(fma2(ab1.x, v.y, ab1.y), v.y, acc[k]);
        }
    }
#pragma unroll
    for (int k = 0; k < Kn; k++) {
        float lo, hi; up2(acc[k], lo, hi);
        l[k] = sp->C[k] + lo + hi;
    }
    softmax5(l, p);
}

// ---------------------------------------------------------------- accumulate (E-step + partial M-step sums)
__launch_bounds__(256, 3)
__global__ void accum_kernel(const float* __restrict__ data) {
    __shared__ EStepSmem sp;
    __shared__ __align__(16) float sP[Kn][TILE];   // posteriors transposed [k][t]
    __shared__ float sred[8 * 210];

    const int tid  = threadIdx.x;
    const int b    = blockIdx.y;
    const int wid  = tid >> 5;
    const int lane = tid & 31;

    load_params_smem(&sp, b, tid);

    ull Sx2[Kn]  = {0, 0, 0, 0, 0};   // f32x2 lane-paired accumulators (lane = feature)
    ull Sxx2[Kn] = {0, 0, 0, 0, 0};
    const ull ONE2 = pk2(1.0f, 1.0f);
    const float* dbase = data + (size_t)b * Nn * Fn;

    for (int tile = blockIdx.x; tile < NTILES; tile += GRIDX) {
        const int base   = tile * TILE;
        const int nvalid = min(TILE, Nn - base);

        __syncthreads();   // sP safe to overwrite (also orders param load on iter 0)

        // -------- phase 1: thread handles points (base+tid) and (base+tid+256), j-outer
        if (nvalid == TILE) {
            const ulonglong2* xa =
                reinterpret_cast<const ulonglong2*>(dbase + (size_t)(base + tid) * Fn);
            const ulonglong2* xb = xa + (256 * Fn / 4);   // +256 points
            ull acc0[Kn] = {0, 0, 0, 0, 0};
            ull acc1[Kn] = {0, 0, 0, 0, 0};
#pragma unroll
            for (int jj = 0; jj < 5; jj++) {
                ulonglong2 va = __ldg(xa + jj);
                ulonglong2 vb = __ldg(xb + jj);
#pragma unroll
                for (int k = 0; k < Kn; k++) {
                    ulonglong2 ab0 = sp.AB[k][2 * jj];       // one LDS.128, two points
                    ulonglong2 ab1 = sp.AB[k][2 * jj + 1];
                    acc0[k] = fma2(fma2(ab0.x, va.x, ab0.y), va.x, acc0[k]);
                    acc0[k] = fma2(fma2(ab1.x, va.y, ab1.y), va.y, acc0[k]);
                    acc1[k] = fma2(fma2(ab0.x, vb.x, ab0.y), vb.x, acc1[k]);
                    acc1[k] = fma2(fma2(ab1.x, vb.y, ab1.y), vb.y, acc1[k]);
                }
            }
            float la[Kn], lb[Kn];
#pragma unroll
            for (int k = 0; k < Kn; k++) {
                float lo, hi;
                up2(acc0[k], lo, hi); la[k] = sp.C[k] + lo + hi;
                up2(acc1[k], lo, hi); lb[k] = sp.C[k] + lo + hi;
            }
            float pa[Kn], pb[Kn];
            softmax5(la, pa);
            softmax5(lb, pb);
#pragma unroll
            for (int k = 0; k < Kn; k++) sP[k][tid]       = pa[k];
#pragma unroll
            for (int k = 0; k < Kn; k++) sP[k][tid + 256] = pb[k];
        } else {
            // tail tile (one per b): per-point fallback
            if (tid < nvalid) {
                float l[Kn], p[Kn];
                loglik_softmax1(&sp, dbase + (size_t)(base + tid) * Fn, l, p);
#pragma unroll
                for (int k = 0; k < Kn; k++) sP[k][tid] = p[k];
            }
            if (tid + 256 < nvalid) {
                float l[Kn], p[Kn];
                loglik_softmax1(&sp, dbase + (size_t)(base + tid + 256) * Fn, l, p);
#pragma unroll
                for (int k = 0; k < Kn; k++) sP[k][tid + 256] = p[k];
            }
        }
        __syncthreads();

        // -------- phase 2: warp owns 64 points (2 at a time via f32x2), lane owns feature f
        const int t0w = wid * 64;
        int rem = nvalid - t0w;
        int cnt = rem < 0 ? 0 : (rem > 64 ? 64 : rem);
        const bool act = lane < 20;
        const float* xr = dbase + (size_t)(base + t0w) * Fn + (act ? lane : 0);

        if (cnt == 64) {
#pragma unroll 8
            for (int i = 0; i < 64; i += 2) {
                float xa = xr[i * Fn];            // L1 hit (loaded by phase 1)
                float xb = xr[i * Fn + Fn];
                ull x2p = act ? pk2(xa, xb) : ONE2;
                ull xx2 = mul2(x2p, x2p);
#pragma unroll
                for (int k = 0; k < Kn; k++) {
                    ull p2 = *reinterpret_cast<const ull*>(&sP[k][t0w + i]);  // broadcast LDS.64
                    Sx2[k]  = fma2(p2, x2p, Sx2[k]);
                    Sxx2[k] = fma2(p2, xx2, Sxx2[k]);
                }
            }
        } else if (cnt > 0) {
            int i = 0;
            for (; i + 1 < cnt; i += 2) {
                float xa = xr[i * Fn];
                float xb = xr[i * Fn + Fn];
                ull x2p = act ? pk2(xa, xb) : ONE2;
                ull xx2 = mul2(x2p, x2p);
#pragma unroll
                for (int k = 0; k < Kn; k++) {
                    ull p2 = *reinterpret_cast<const ull*>(&sP[k][t0w + i]);
                    Sx2[k]  = fma2(p2, x2p, Sx2[k]);
                    Sxx2[k] = fma2(p2, xx2, Sxx2[k]);
                }
            }
            if (i < cnt) {   // odd tail
                float xa = xr[i * Fn];
                ull x2p = act ? pk2(xa, 0.0f) : pk2(1.0f, 0.0f);
                ull xx2 = mul2(x2p, x2p);
#pragma unroll
                for (int k = 0; k < Kn; k++) {
                    ull p2 = pk2(sP[k][t0w + i], 0.0f);
                    Sx2[k]  = fma2(p2, x2p, Sx2[k]);
                    Sxx2[k] = fma2(p2, xx2, Sxx2[k]);
                }
            }
        }
    }

    // -------- block reduction + one atomicAdd per entry
    __syncthreads();
    if (lane < 21) {   // lane 20 carries the Sigma-p (ones-feature) column
#pragma unroll
        for (int k = 0; k < Kn; k++) {
            float lo, hi; up2(Sx2[k], lo, hi);
            sred[wid * 210 + k * 21 + lane] = lo + hi;
        }
#pragma unroll
        for (int k = 0; k < Kn; k++) {
            float lo, hi; up2(Sxx2[k], lo, hi);
            sred[wid * 210 + 105 + k * 21 + lane] = lo + hi;
        }
    }
    __syncthreads();
    if (tid < 210) {
        float v = 0.0f;
#pragma unroll
        for (int w = 0; w < 8; w++) v += sred[w * 210 + tid];
        atomicAdd(&g_acc[b * 210 + tid], v);
    }
}

// ---------------------------------------------------------------- M-step finalize (+ param refresh, + output on last iter)
__global__ void finalize_kernel(int is_last, float* __restrict__ out_means,
                                float* __restrict__ out_var, float* __restrict__ out_pi) {
    int tid = threadIdx.x;
    __shared__ float sS[Bn * Kn];
    if (tid < Bn * Kn) {
        int b = tid / Kn, k = tid - b * Kn;
        sS[tid] = g_acc[b * 210 + k * 21 + 20];
    }
    __syncthreads();
    if (tid < Bn * Kn) {
        int b = tid / Kn, k = tid - b * Kn;
        float S = sS[tid];
        float sum = sS[b * Kn + 0] + sS[b * Kn + 1] + sS[b * Kn + 2] +
                    sS[b * Kn + 3] + sS[b * Kn + 4];
        // pi = (S/N) / max(sum|S|/N, 1e-12) == S / max(sum, N*1e-12)
        float pi = S / fmaxf(sum, (float)Nn * 1e-12f);
        float dS = S + 1e-7f;
        float invdS = 1.0f / dS;

        float mu[Fn], vv[Fn];
#pragma unroll
        for (int f = 0; f < Fn; f++) {
            float sx  = g_acc[b * 210 + k * 21 + f];
            float sxx = g_acc[b * 210 + 105 + k * 21 + f];
            float m = sx * invdS;
            float v = (sxx - 2.0f * m * sx + m * m * S) * invdS + 1e-6f;  // var + EPS_VAR
            mu[f] = m;
            vv[f] = v;
        }
        write_params(b, k, logf(pi), mu, vv);
        if (is_last) {
#pragma unroll
            for (int f = 0; f < Fn; f++) {
                out_means[(b * Kn + k) * Fn + f] = mu[f];
                out_var[(b * Kn + k) * Fn + f]   = vv[f];
            }
            out_pi[b * Kn + k] = pi;
        }
    }
    __syncthreads();
    for (int i = tid; i < Bn * 210; i += blockDim.x) g_acc[i] = 0.0f;
}

// ---------------------------------------------------------------- final E-step: write ll + post [B,N,K] via smem-staged float4
__launch_bounds__(TO)
__global__ void estep_out_kernel(const float* __restrict__ data,
                                 float* __restrict__ out_ll,
                                 float* __restrict__ out_post) {
    __shared__ EStepSmem sp;
    __shared__ __align__(16) float sLL[TO * Kn];
    __shared__ __align__(16) float sPP[TO * Kn];
    const int tid = threadIdx.x;
    const int b   = blockIdx.y;
    load_params_smem(&sp, b, tid);
    __syncthreads();

    const int base = blockIdx.x * TO;
    const int n = base + tid;
    if (n < Nn) {
        float l[Kn], p[Kn];
        loglik_softmax1(&sp, data + ((size_t)b * Nn + n) * Fn, l, p);
#pragma unroll
        for (int k = 0; k < Kn; k++) sLL[tid * Kn + k] = l[k];
#pragma unroll
        for (int k = 0; k < Kn; k++) sPP[tid * Kn + k] = p[k];
    }
    __syncthreads();

    const int nvalid = min(TO, Nn - base);
    const int nf4 = nvalid * Kn / 4;                 // nvalid*5 always /4 (nvalid 256 or 128)
    const size_t off = ((size_t)b * Nn + base) * Kn; // multiple of 4 floats -> 16B aligned
    float4* dll = reinterpret_cast<float4*>(out_ll + off);
    float4* dpp = reinterpret_cast<float4*>(out_post + off);
    const float4* sll4 = reinterpret_cast<const float4*>(sLL);
    const float4* spp4 = reinterpret_cast<const float4*>(sPP);
    for (int i = tid; i < nf4; i += TO) dll[i] = sll4[i];
    for (int i = tid; i < nf4; i += TO) dpp[i] = spp4[i];
}

// ---------------------------------------------------------------- launch
extern "C" void kernel_launch(void* const* d_in, const int* in_sizes, int n_in,
                              void* d_out, int out_size) {
    const float* data  = (const float*)d_in[0];
    const float* means = (const float*)d_in[1];
    const float* var   = (const float*)d_in[2];
    const float* pri   = (const float*)d_in[3];

    float* out = (float*)d_out;
    size_t NK = (size_t)Bn * Nn * Kn;                 // 3,200,000
    float* out_ll    = out;
    float* out_post  = out + NK;
    float* out_means = out + 2 * NK;
    float* out_var   = out_means + Bn * Kn * Fn;      // +800
    float* out_pi    = out_var   + Bn * Kn * Fn;      // +800

    init_kernel<<<1, 256>>>(means, var, pri);
    for (int it = 0; it < NITER; it++) {
        accum_kernel<<<dim3(GRIDX, Bn), 256>>>(data);
        finalize_kernel<<<1, 256>>>(it == NITER - 1 ? 1 : 0, out_means, out_var, out_pi);
    }
    estep_out_kernel<<<dim3(NTO, Bn), TO>>>(data, out_ll, out_post);
}

// round 8
// speedup vs baseline: 1.1972x; 1.0360x over previous
#include <cuda_runtime.h>

typedef unsigned long long ull;

// GMM EM on GB300. B=8, N=80000, K=5, F=20, 5 iterations + final E-step.
// Inputs:  d_in[0]=data [B,N,F], d_in[1]=means [B,K,F], d_in[2]=variance [B,K,F], d_in[3]=prior [B,K]
// Output:  concat( ll [B,N,K], post [B,N,K], means [B,K,F], var [B,K,F], pi [B,K] ) fp32

#define Bn 8
#define Nn 80000
#define Kn 5
#define Fn 20
#define NITER 5
#define THR 128                            // threads per accum block
#define TILE 256                           // points per tile (2 per thread)
#define NTILES ((Nn + TILE - 1) / TILE)    // 313 (last tile: 128 valid)
#define GRIDX 111                          // 111*8 = 888 blocks = one wave at 6 blocks/SM
#define TO 256                             // estep_out tile
#define NTO ((Nn + TO - 1) / TO)           // 313

// Per-(b): Sx[k][f] at k*21+f (f==20 is the constant-1 feature -> Sx == cluster size S),
//          Sxx[k][f] at 105 + k*21+f.
__device__ float g_acc[Bn * 210];

// Per-(b,k) E-step params, 44 floats (11 float4):
// float4 j (j=0..9): {A_{2j}, A_{2j+1}, B_{2j}, B_{2j+1}} with A_f = -0.5/(var+eps), B_f = mu/(var+eps)
// [40] = C = log(pi) - 0.5*sum log(2pi var) - 0.5*sum mu^2/(var+eps)
__device__ float4 g_params4[Bn * Kn * 11];

// ---------------------------------------------------------------- f32x2 helpers
__device__ __forceinline__ ull pk2(float lo, float hi) {
    ull r; asm("mov.b64 %0,{%1,%2};" : "=l"(r) : "f"(lo), "f"(hi)); return r;
}
__device__ __forceinline__ void up2(ull v, float& lo, float& hi) {
    asm("mov.b64 {%0,%1},%2;" : "=f"(lo), "=f"(hi) : "l"(v));
}
__device__ __forceinline__ ull fma2(ull a, ull b, ull c) {
    ull d; asm("fma.rn.f32x2 %0,%1,%2,%3;" : "=l"(d) : "l"(a), "l"(b), "l"(c)); return d;
}
__device__ __forceinline__ ull mul2(ull a, ull b) {
    ull d; asm("mul.rn.f32x2 %0,%1,%2;" : "=l"(d) : "l"(a), "l"(b)); return d;
}

// ---------------------------------------------------------------- params writer
__device__ __forceinline__ void write_params(int b, int k, float C_base,
                                             const float* mu, const float* var) {
    float* gp = reinterpret_cast<float*>(g_params4) + (b * Kn + k) * 44;
    float C = C_base;
    float A[Fn], Bc[Fn];
#pragma unroll
    for (int f = 0; f < Fn; f++) {
        float v = var[f];
        float m = mu[f];
        float ic = 1.0f / (v + 1e-6f);
        C += -0.5f * logf(6.283185307179586f * v) - 0.5f * ic * m * m;
        A[f]  = -0.5f * ic;
        Bc[f] = ic * m;
    }
#pragma unroll
    for (int j = 0; j < 10; j++) {
        gp[4 * j]     = A[2 * j];
        gp[4 * j + 1] = A[2 * j + 1];
        gp[4 * j + 2] = Bc[2 * j];
        gp[4 * j + 3] = Bc[2 * j + 1];
    }
    gp[40] = C;
}

// ---------------------------------------------------------------- init
__global__ void init_kernel(const float* __restrict__ means,
                            const float* __restrict__ var,
                            const float* __restrict__ pri) {
    int tid = threadIdx.x;
    if (tid < Bn * Kn) {
        int b = tid / Kn, k = tid - b * Kn;
        float mu[Fn], vv[Fn];
#pragma unroll
        for (int f = 0; f < Fn; f++) {
            mu[f] = means[(b * Kn + k) * Fn + f];
            vv[f] = var[(b * Kn + k) * Fn + f];
        }
        write_params(b, k, logf(pri[b * Kn + k]), mu, vv);
    }
    for (int i = tid; i < Bn * 210; i += blockDim.x) g_acc[i] = 0.0f;
}

// ---------------------------------------------------------------- E-step core
struct EStepSmem {
    ulonglong2 AB[Kn][10];   // .x = packed(A_{2j},A_{2j+1}), .y = packed(B_{2j},B_{2j+1})
    float      C[Kn];
};

__device__ __forceinline__ void load_params_smem(EStepSmem* sp, int b, int tid) {
    if (tid < Kn * 11) {
        int k = tid / 11, q = tid - k * 11;
        float4 v = g_params4[(b * Kn + k) * 11 + q];
        if (q < 10) {
            ulonglong2 w;
            w.x = pk2(v.x, v.y);
            w.y = pk2(v.z, v.w);
            sp->AB[k][q] = w;
        } else {
            sp->C[k] = v.x;
        }
    }
}

__device__ __forceinline__ void softmax5(const float* l, float* p) {
    float m = l[0];
#pragma unroll
    for (int k = 1; k < Kn; k++) m = fmaxf(m, l[k]);
    float s = 0.0f;
#pragma unroll
    for (int k = 0; k < Kn; k++) { p[k] = __expf(l[k] - m); s += p[k]; }
    float inv = __fdividef(1.0f, s);
#pragma unroll
    for (int k = 0; k < Kn; k++) p[k] *= inv;
}

// single-point log-lik + softmax from a generic pointer (smem or gmem)
__device__ __forceinline__ void loglik_softmax1(const EStepSmem* sp,
                                                const ulonglong2* __restrict__ xp,
                                                float* l, float* p) {
    ull acc[Kn] = {0, 0, 0, 0, 0};
#pragma unroll
    for (int jj = 0; jj < 5; jj++) {
        ulonglong2 v = xp[jj];
#pragma unroll
        for (int k = 0; k < Kn; k++) {
            ulonglong2 ab0 = sp->AB[k][2 * jj];
            ulonglong2 ab1 = sp->AB[k][2 * jj + 1];
            acc[k] = fma2(fma2(ab0.x, v.x, ab0.y), v.x, acc[k]);
            acc[k] = fma2(fma2(ab1.x, v.y, ab1.y), v.y, acc[k]);
        }
    }
#pragma unroll
    for (int k = 0; k < Kn; k++) {
        float lo, hi; up2(acc[k], lo, hi);
        l[k] = sp->C[k] + lo + hi;
    }
    softmax5(l, p);
}

// ---------------------------------------------------------------- accumulate (E-step + partial M-step sums)
__launch_bounds__(THR, 6)
__global__ void accum_kernel(const float* __restrict__ data) {
    __shared__ EStepSmem sp;
    __shared__ __align__(16) float sX[TILE * Fn];   // staged tile, point-major (80B rows), 20KB
    __shared__ __align__(16) float sP[Kn][TILE];    // posteriors transposed [k][t], 5KB
    __shared__ float sred[4 * 210];

    const int tid  = threadIdx.x;
    const int b    = blockIdx.y;
    const int wid  = tid >> 5;
    const int lane = tid & 31;

    load_params_smem(&sp, b, tid);

    ull Sx2[Kn]  = {0, 0, 0, 0, 0};   // f32x2 lane-paired accumulators (lane = feature)
    ull Sxx2[Kn] = {0, 0, 0, 0, 0};
    const ull ONE2 = pk2(1.0f, 1.0f);
    const float* dbase = data + (size_t)b * Nn * Fn;

    for (int tile = blockIdx.x; tile < NTILES; tile += GRIDX) {
        const int base   = tile * TILE;
        const int nvalid = min(TILE, Nn - base);   // 256 or 128 (last tile only)

        __syncthreads();   // smem safe to overwrite

        // -------- phase 0: coalesced staging of tile into smem (float4)
        {
            const float4* src4 = reinterpret_cast<const float4*>(dbase + base * Fn);
            float4* sx4 = reinterpret_cast<float4*>(sX);
            const int nf4 = nvalid * (Fn / 4);     // 1280 or 640
#pragma unroll
            for (int u = 0; u < TILE * (Fn / 4) / THR; u++) {
                int i = tid + u * THR;
                if (i < nf4) sx4[i] = __ldg(src4 + i);
            }
        }
        __syncthreads();

        // -------- phase 1: thread handles points tid and tid+128 (x from smem), j-outer
        if (nvalid == TILE) {
            const ulonglong2* xa = reinterpret_cast<const ulonglong2*>(sX + tid * Fn);
            const ulonglong2* xb = reinterpret_cast<const ulonglong2*>(sX + (tid + THR) * Fn);
            ull acc0[Kn] = {0, 0, 0, 0, 0};
            ull acc1[Kn] = {0, 0, 0, 0, 0};
#pragma unroll
            for (int jj = 0; jj < 5; jj++) {
                ulonglong2 va = xa[jj];
                ulonglong2 vb = xb[jj];
#pragma unroll
                for (int k = 0; k < Kn; k++) {
                    ulonglong2 ab0 = sp.AB[k][2 * jj];       // one LDS.128, two points
                    ulonglong2 ab1 = sp.AB[k][2 * jj + 1];
                    acc0[k] = fma2(fma2(ab0.x, va.x, ab0.y), va.x, acc0[k]);
                    acc0[k] = fma2(fma2(ab1.x, va.y, ab1.y), va.y, acc0[k]);
                    acc1[k] = fma2(fma2(ab0.x, vb.x, ab0.y), vb.x, acc1[k]);
                    acc1[k] = fma2(fma2(ab1.x, vb.y, ab1.y), vb.y, acc1[k]);
                }
            }
            float la[Kn], lb[Kn];
#pragma unroll
            for (int k = 0; k < Kn; k++) {
                float lo, hi;
                up2(acc0[k], lo, hi); la[k] = sp.C[k] + lo + hi;
                up2(acc1[k], lo, hi); lb[k] = sp.C[k] + lo + hi;
            }
            float pa[Kn], pb[Kn];
            softmax5(la, pa);
            softmax5(lb, pb);
#pragma unroll
            for (int k = 0; k < Kn; k++) sP[k][tid]       = pa[k];
#pragma unroll
            for (int k = 0; k < Kn; k++) sP[k][tid + THR] = pb[k];
        } else {
            // tail tile: nvalid == 128 == THR, every thread one point
            float l[Kn], p[Kn];
            loglik_softmax1(&sp, reinterpret_cast<const ulonglong2*>(sX + tid * Fn), l, p);
#pragma unroll
            for (int k = 0; k < Kn; k++) sP[k][tid] = p[k];
        }
        __syncthreads();

        // -------- phase 2: warp owns 64 points (4 at a time), lane owns feature f
        const int t0w = wid * 64;
        if (t0w < nvalid) {                       // cnt is always 0 or 64
            const bool act = lane < 20;
            const float* xcol = sX + t0w * Fn + (act ? lane : 0);
#pragma unroll 4
            for (int i = 0; i < 64; i += 4) {
                float x0 = xcol[(i + 0) * Fn];
                float x1 = xcol[(i + 1) * Fn];
                float x2 = xcol[(i + 2) * Fn];
                float x3 = xcol[(i + 3) * Fn];
                ull xp01 = act ? pk2(x0, x1) : ONE2;
                ull xp23 = act ? pk2(x2, x3) : ONE2;
                ull xx01 = mul2(xp01, xp01);
                ull xx23 = mul2(xp23, xp23);
#pragma unroll
                for (int k = 0; k < Kn; k++) {
                    ulonglong2 pp =
                        *reinterpret_cast<const ulonglong2*>(&sP[k][t0w + i]);  // broadcast LDS.128
                    Sx2[k]  = fma2(pp.x, xp01, Sx2[k]);
                    Sx2[k]  = fma2(pp.y, xp23, Sx2[k]);
                    Sxx2[k] = fma2(pp.x, xx01, Sxx2[k]);
                    Sxx2[k] = fma2(pp.y, xx23, Sxx2[k]);
                }
            }
        }
    }

    // -------- block reduction + one atomicAdd per entry
    __syncthreads();
    if (lane < 21) {   // lane 20 carries the Sigma-p (ones-feature) column
#pragma unroll
        for (int k = 0; k < Kn; k++) {
            float lo, hi; up2(Sx2[k], lo, hi);
            sred[wid * 210 + k * 21 + lane] = lo + hi;
        }
#pragma unroll
        for (int k = 0; k < Kn; k++) {
            float lo, hi; up2(Sxx2[k], lo, hi);
            sred[wid * 210 + 105 + k * 21 + lane] = lo + hi;
        }
    }
    __syncthreads();
    for (int i = tid; i < 210; i += THR) {
        float v = sred[i] + sred[210 + i] + sred[420 + i] + sred[630 + i];
        atomicAdd(&g_acc[b * 210 + i], v);
    }
}

// ---------------------------------------------------------------- M-step finalize (+ param refresh, + output on last iter)
__global__ void finalize_kernel(int is_last, float* __restrict__ out_means,
                                float* __restrict__ out_var, float* __restrict__ out_pi) {
    int tid = threadIdx.x;
    __shared__ float sS[Bn * Kn];
    if (tid < Bn * Kn) {
        int b = tid / Kn, k = tid - b * Kn;
        sS[tid] = g_acc[b * 210 + k * 21 + 20];
    }
    __syncthreads();
    if (tid < Bn * Kn) {
        int b = tid / Kn, k = tid - b * Kn;
        float S = sS[tid];
        float sum = sS[b * Kn + 0] + sS[b * Kn + 1] + sS[b * Kn + 2] +
                    sS[b * Kn + 3] + sS[b * Kn + 4];
        // pi = (S/N) / max(sum|S|/N, 1e-12) == S / max(sum, N*1e-12)
        float pi = S / fmaxf(sum, (float)Nn * 1e-12f);
        float dS = S + 1e-7f;
        float invdS = 1.0f / dS;

        float mu[Fn], vv[Fn];
#pragma unroll
        for (int f = 0; f < Fn; f++) {
            float sx  = g_acc[b * 210 + k * 21 + f];
            float sxx = g_acc[b * 210 + 105 + k * 21 + f];
            float m = sx * invdS;
            float v = (sxx - 2.0f * m * sx + m * m * S) * invdS + 1e-6f;  // var + EPS_VAR
            mu[f] = m;
            vv[f] = v;
        }
        write_params(b, k, logf(pi), mu, vv);
        if (is_last) {
#pragma unroll
            for (int f = 0; f < Fn; f++) {
                out_means[(b * Kn + k) * Fn + f] = mu[f];
                out_var[(b * Kn + k) * Fn + f]   = vv[f];
            }
            out_pi[b * Kn + k] = pi;
        }
    }
    __syncthreads();
    for (int i = tid; i < Bn * 210; i += blockDim.x) g_acc[i] = 0.0f;
}

// ---------------------------------------------------------------- final E-step: write ll + post [B,N,K] via smem-staged float4
__launch_bounds__(TO)
__global__ void estep_out_kernel(const float* __restrict__ data,
                                 float* __restrict__ out_ll,
                                 float* __restrict__ out_post) {
    __shared__ EStepSmem sp;
    __shared__ __align__(16) float sLL[TO * Kn];
    __shared__ __align__(16) float sPP[TO * Kn];
    const int tid = threadIdx.x;
    const int b   = blockIdx.y;
    load_params_smem(&sp, b, tid);
    __syncthreads();

    const int base = blockIdx.x * TO;
    const int n = base + tid;
    if (n < Nn) {
        float l[Kn], p[Kn];
        loglik_softmax1(&sp,
            reinterpret_cast<const ulonglong2*>(data + ((size_t)b * Nn + n) * Fn), l, p);
#pragma unroll
        for (int k = 0; k < Kn; k++) sLL[tid * Kn + k] = l[k];
#pragma unroll
        for (int k = 0; k < Kn; k++) sPP[tid * Kn + k] = p[k];
    }
    __syncthreads();

    const int nvalid = min(TO, Nn - base);
    const int nf4 = nvalid * Kn / 4;                 // nvalid*5 always /4 (nvalid 256 or 128)
    const size_t off = ((size_t)b * Nn + base) * Kn; // multiple of 4 floats -> 16B aligned
    float4* dll = reinterpret_cast<float4*>(out_ll + off);
    float4* dpp = reinterpret_cast<float4*>(out_post + off);
    const float4* sll4 = reinterpret_cast<const float4*>(sLL);
    const float4* spp4 = reinterpret_cast<const float4*>(sPP);
    for (int i = tid; i < nf4; i += TO) dll[i] = sll4[i];
    for (int i = tid; i < nf4; i += TO) dpp[i] = spp4[i];
}

// ---------------------------------------------------------------- launch
extern "C" void kernel_launch(void* const* d_in, const int* in_sizes, int n_in,
                              void* d_out, int out_size) {
    const float* data  = (const float*)d_in[0];
    const float* means = (const float*)d_in[1];
    const float* var   = (const float*)d_in[2];
    const float* pri   = (const float*)d_in[3];

    float* out = (float*)d_out;
    size_t NK = (size_t)Bn * Nn * Kn;                 // 3,200,000
    float* out_ll    = out;
    float* out_post  = out + NK;
    float* out_means = out + 2 * NK;
    float* out_var   = out_means + Bn * Kn * Fn;      // +800
    float* out_pi    = out_var   + Bn * Kn * Fn;      // +800

    init_kernel<<<1, 256>>>(means, var, pri);
    for (int it = 0; it < NITER; it++) {
        accum_kernel<<<dim3(GRIDX, Bn), THR>>>(data);
        finalize_kernel<<<1, 256>>>(it == NITER - 1 ? 1 : 0, out_means, out_var, out_pi);
    }
    estep_out_kernel<<<dim3(NTO, Bn), TO>>>(data, out_ll, out_post);
}

// round 12
// speedup vs baseline: 1.2137x; 1.0137x over previous
#include <cuda_runtime.h>

typedef unsigned long long ull;

// GMM EM on GB300. B=8, N=80000, K=5, F=20, 5 iterations + final E-step.
// Inputs:  d_in[0]=data [B,N,F], d_in[1]=means [B,K,F], d_in[2]=variance [B,K,F], d_in[3]=prior [B,K]
// Output:  concat( ll [B,N,K], post [B,N,K], means [B,K,F], var [B,K,F], pi [B,K] ) fp32

#define Bn 8
#define Nn 80000
#define Kn 5
#define Fn 20
#define NITER 5
#define THR 128                            // threads per accum block
#define TILE 256                           // points per tile (2 per thread)
#define NTILES ((Nn + TILE - 1) / TILE)    // 313 (last tile: 128 valid)
#define GRIDX 111                          // 111*8 = 888 blocks = one wave at 6 blocks/SM
#define TO 256                             // estep_out tile
#define NTO ((Nn + TO - 1) / TO)           // 313

// Per-(b): Sx[k][f] at k*21+f (f==20 is the constant-1 feature -> Sx == cluster size S),
//          Sxx[k][f] at 105 + k*21+f.  Zero-initialized; reset by the finalize block each iter.
__device__ float g_acc[Bn * 210];
__device__ int   g_cnt[Bn];

// Per-(b,k) E-step params, 44 floats (11 float4):
// float4 j (j=0..9): {A_{2j}, A_{2j+1}, B_{2j}, B_{2j+1}} with A_f = -0.5/(var+eps), B_f = mu/(var+eps)
// [40] = C = log(pi) - 0.5*sum log(2pi var) - 0.5*sum mu^2/(var+eps)
__device__ float4 g_params4[Bn * Kn * 11];

// ---------------------------------------------------------------- f32x2 helpers
__device__ __forceinline__ ull pk2(float lo, float hi) {
    ull r; asm("mov.b64 %0,{%1,%2};" : "=l"(r) : "f"(lo), "f"(hi)); return r;
}
__device__ __forceinline__ void up2(ull v, float& lo, float& hi) {
    asm("mov.b64 {%0,%1},%2;" : "=f"(lo), "=f"(hi) : "l"(v));
}
__device__ __forceinline__ ull fma2(ull a, ull b, ull c) {
    ull d; asm("fma.rn.f32x2 %0,%1,%2,%3;" : "=l"(d) : "l"(a), "l"(b), "l"(c)); return d;
}
__device__ __forceinline__ ull mul2(ull a, ull b) {
    ull d; asm("mul.rn.f32x2 %0,%1,%2;" : "=l"(d) : "l"(a), "l"(b)); return d;
}

// ---------------------------------------------------------------- E-step smem params
struct EStepSmem {
    ulonglong2 AB[Kn][10];   // .x = packed(A_{2j},A_{2j+1}), .y = packed(B_{2j},B_{2j+1})
    float      C[Kn];
};

__device__ __forceinline__ void load_params_smem(EStepSmem* sp, int b, int tid) {
    if (tid < Kn * 11) {
        int k = tid / 11, q = tid - k * 11;
        float4 v = g_params4[(b * Kn + k) * 11 + q];
        if (q < 10) {
            ulonglong2 w;
            w.x = pk2(v.x, v.y);
            w.y = pk2(v.z, v.w);
            sp->AB[k][q] = w;
        } else {
            sp->C[k] = v.x;
        }
    }
}

__device__ __forceinline__ void softmax5(const float* l, float* p) {
    float m = l[0];
#pragma unroll
    for (int k = 1; k < Kn; k++) m = fmaxf(m, l[k]);
    float s = 0.0f;
#pragma unroll
    for (int k = 0; k < Kn; k++) { p[k] = __expf(l[k] - m); s += p[k]; }
    float inv = __fdividef(1.0f, s);
#pragma unroll
    for (int k = 0; k < Kn; k++) p[k] *= inv;
}

// single-point log-lik + softmax from a generic pointer (smem or gmem)
__device__ __forceinline__ void loglik_softmax1(const EStepSmem* sp,
                                                const ulonglong2* __restrict__ xp,
                                                float* l, float* p) {
    ull acc[Kn] = {0, 0, 0, 0, 0};
#pragma unroll
    for (int jj = 0; jj < 5; jj++) {
        ulonglong2 v = xp[jj];
#pragma unroll
        for (int k = 0; k < Kn; k++) {
            ulonglong2 ab0 = sp->AB[k][2 * jj];
            ulonglong2 ab1 = sp->AB[k][2 * jj + 1];
            acc[k] = fma2(fma2(ab0.x, v.x, ab0.y), v.x, acc[k]);
            acc[k] = fma2(fma2(ab1.x, v.y, ab1.y), v.y, acc[k]);
        }
    }
#pragma unroll
    for (int k = 0; k < Kn; k++) {
        float lo, hi; up2(acc[k], lo, hi);
        l[k] = sp->C[k] + lo + hi;
    }
    softmax5(l, p);
}

// two-point log-lik + softmax sharing param loads (j-outer)
__device__ __forceinline__ void loglik_softmax2(const EStepSmem* sp,
                                                const ulonglong2* __restrict__ xa,
                                                const ulonglong2* __restrict__ xb,
                                                float* la, float* pa,
                                                float* lb, float* pb) {
    ull acc0[Kn] = {0, 0, 0, 0, 0};
    ull acc1[Kn] = {0, 0, 0, 0, 0};
#pragma unroll
    for (int jj = 0; jj < 5; jj++) {
        ulonglong2 va = xa[jj];
        ulonglong2 vb = xb[jj];
#pragma unroll
        for (int k = 0; k < Kn; k++) {
            ulonglong2 ab0 = sp->AB[k][2 * jj];       // one LDS.128, two points
            ulonglong2 ab1 = sp->AB[k][2 * jj + 1];
            acc0[k] = fma2(fma2(ab0.x, va.x, ab0.y), va.x, acc0[k]);
            acc0[k] = fma2(fma2(ab1.x, va.y, ab1.y), va.y, acc0[k]);
            acc1[k] = fma2(fma2(ab0.x, vb.x, ab0.y), vb.x, acc1[k]);
            acc1[k] = fma2(fma2(ab1.x, vb.y, ab1.y), vb.y, acc1[k]);
        }
    }
#pragma unroll
    for (int k = 0; k < Kn; k++) {
        float lo, hi;
        up2(acc0[k], lo, hi); la[k] = sp->C[k] + lo + hi;
        up2(acc1[k], lo, hi); lb[k] = sp->C[k] + lo + hi;
    }
    softmax5(la, pa);
    softmax5(lb, pb);
}

// ---------------------------------------------------------------- fused accum + finalize
// it==0: params computed per-block from raw inputs (no init kernel needed).
// End:   last block per b performs the M-step finalize, refreshes g_params4,
//        writes means/var/pi outputs on the last iteration, resets g_acc/g_cnt.
__launch_bounds__(THR, 6)
__global__ void accum_kernel(const float* __restrict__ data,
                             const float* __restrict__ in_means,
                             const float* __restrict__ in_var,
                             const float* __restrict__ in_pri,
                             int it,
                             float* __restrict__ out_means,
                             float* __restrict__ out_var,
                             float* __restrict__ out_pi) {
    __shared__ EStepSmem sp;
    __shared__ __align__(16) float sX[TILE * Fn];   // staged tile, point-major (80B rows), 20KB
    __shared__ __align__(16) float sP[Kn][TILE];    // posteriors transposed [k][t], 5KB
    __shared__ float sred[4 * 210];
    __shared__ float sCp[Kn][10];
    __shared__ float sS[Kn];
    __shared__ float sSum;
    __shared__ int   sIsLast;

    const int tid  = threadIdx.x;
    const int b    = blockIdx.y;
    const int wid  = tid >> 5;
    const int lane = tid & 31;

    // ---- param acquisition
    if (it == 0) {
        // bootstrap from raw inputs (every block, redundant but tiny)
        if (tid < 50) {
            int k = tid / 10, j = tid - k * 10;
            const float* mu = in_means + (b * Kn + k) * Fn + 2 * j;
            const float* vv = in_var   + (b * Kn + k) * Fn + 2 * j;
            float v0 = vv[0], v1 = vv[1], m0 = mu[0], m1 = mu[1];
            float ic0 = 1.0f / (v0 + 1e-6f);
            float ic1 = 1.0f / (v1 + 1e-6f);
            sp.AB[k][j].x = pk2(-0.5f * ic0, -0.5f * ic1);
            sp.AB[k][j].y = pk2(ic0 * m0, ic1 * m1);
            sCp[k][j] = -0.5f * (logf(6.283185307179586f * v0) +
                                 logf(6.283185307179586f * v1))
                        - 0.5f * (ic0 * m0 * m0 + ic1 * m1 * m1);
        }
        __syncthreads();
        if (tid < Kn) {
            float C = logf(in_pri[b * Kn + tid]);
#pragma unroll
            for (int j = 0; j < 10; j++) C += sCp[tid][j];
            sp.C[tid] = C;
        }
    } else {
        load_params_smem(&sp, b, tid);
    }

    ull Sx2[Kn]  = {0, 0, 0, 0, 0};   // f32x2 lane-paired accumulators (lane = feature)
    ull Sxx2[Kn] = {0, 0, 0, 0, 0};
    const ull ONE2 = pk2(1.0f, 1.0f);
    const float* dbase = data + (size_t)b * Nn * Fn;

    for (int tile = blockIdx.x; tile < NTILES; tile += GRIDX) {
        const int base   = tile * TILE;
        const int nvalid = min(TILE, Nn - base);   // 256 or 128 (last tile only)

        __syncthreads();   // smem safe to overwrite (also orders param setup on first iter)

        // -------- phase 0: coalesced staging of tile into smem (float4)
        {
            const float4* src4 = reinterpret_cast<const float4*>(dbase + base * Fn);
            float4* sx4 = reinterpret_cast<float4*>(sX);
            const int nf4 = nvalid * (Fn / 4);     // 1280 or 640
#pragma unroll
            for (int u = 0; u < TILE * (Fn / 4) / THR; u++) {
                int i = tid + u * THR;
                if (i < nf4) sx4[i] = __ldg(src4 + i);
            }
        }
        __syncthreads();

        // -------- phase 1: thread handles points tid and tid+128 (x from smem), j-outer
        if (nvalid == TILE) {
            float la[Kn], lb[Kn], pa[Kn], pb[Kn];
            loglik_softmax2(&sp,
                reinterpret_cast<const ulonglong2*>(sX + tid * Fn),
                reinterpret_cast<const ulonglong2*>(sX + (tid + THR) * Fn),
                la, pa, lb, pb);
#pragma unroll
            for (int k = 0; k < Kn; k++) sP[k][tid]       = pa[k];
#pragma unroll
            for (int k = 0; k < Kn; k++) sP[k][tid + THR] = pb[k];
        } else {
            // tail tile: nvalid == 128 == THR, every thread one point
            float l[Kn], p[Kn];
            loglik_softmax1(&sp, reinterpret_cast<const ulonglong2*>(sX + tid * Fn), l, p);
#pragma unroll
            for (int k = 0; k < Kn; k++) sP[k][tid] = p[k];
        }
        __syncthreads();

        // -------- phase 2: warp owns 64 points (4 at a time), lane owns feature f
        const int t0w = wid * 64;
        if (t0w < nvalid) {                       // cnt is always 0 or 64
            const bool act = lane < 20;
            const float* xcol = sX + t0w * Fn + (act ? lane : 0);
#pragma unroll 4
            for (int i = 0; i < 64; i += 4) {
                float x0 = xcol[(i + 0) * Fn];
                float x1 = xcol[(i + 1) * Fn];
                float x2 = xcol[(i + 2) * Fn];
                float x3 = xcol[(i + 3) * Fn];
                ull xp01 = act ? pk2(x0, x1) : ONE2;
                ull xp23 = act ? pk2(x2, x3) : ONE2;
                ull xx01 = mul2(xp01, xp01);
                ull xx23 = mul2(xp23, xp23);
#pragma unroll
                for (int k = 0; k < Kn; k++) {
                    ulonglong2 pp =
                        *reinterpret_cast<const ulonglong2*>(&sP[k][t0w + i]);  // broadcast LDS.128
                    Sx2[k]  = fma2(pp.x, xp01, Sx2[k]);
                    Sx2[k]  = fma2(pp.y, xp23, Sx2[k]);
                    Sxx2[k] = fma2(pp.x, xx01, Sxx2[k]);
                    Sxx2[k] = fma2(pp.y, xx23, Sxx2[k]);
                }
            }
        }
    }

    // -------- block reduction + one atomicAdd per entry
    __syncthreads();
    if (lane < 21) {   // lane 20 carries the Sigma-p (ones-feature) column
#pragma unroll
        for (int k = 0; k < Kn; k++) {
            float lo, hi; up2(Sx2[k], lo, hi);
            sred[wid * 210 + k * 21 + lane] = lo + hi;
        }
#pragma unroll
        for (int k = 0; k < Kn; k++) {
            float lo, hi; up2(Sxx2[k], lo, hi);
            sred[wid * 210 + 105 + k * 21 + lane] = lo + hi;
        }
    }
    __syncthreads();
    for (int i = tid; i < 210; i += THR) {
        float v = sred[i] + sred[210 + i] + sred[420 + i] + sred[630 + i];
        atomicAdd(&g_acc[b * 210 + i], v);
    }

    // -------- last-block-per-b finalize (M-step + param refresh + output + reset)
    __threadfence();
    __syncthreads();
    if (tid == 0) sIsLast = (atomicAdd(&g_cnt[b], 1) == GRIDX - 1) ? 1 : 0;
    __syncthreads();
    if (!sIsLast) return;
    __threadfence();   // acquire: all blocks' g_acc atomics visible

    const float* gac = &g_acc[b * 210];
    if (tid < Kn) sS[tid] = __ldcg(gac + tid * 21 + 20);
    __syncthreads();
    if (tid == 0) {
        float s = sS[0] + sS[1] + sS[2] + sS[3] + sS[4];
        sSum = fmaxf(s, (float)Nn * 1e-12f);
        g_cnt[b] = 0;                       // reset ticket for next launch
    }
    __syncthreads();
    const int is_last_iter = (it == NITER - 1);
    if (tid < 50) {
        int k = tid / 10, j = tid - k * 10;
        float S = sS[k];
        float invdS = 1.0f / (S + 1e-7f);
        float sx0  = __ldcg(gac + k * 21 + 2 * j);
        float sx1  = __ldcg(gac + k * 21 + 2 * j + 1);
        float sxx0 = __ldcg(gac + 105 + k * 21 + 2 * j);
        float sxx1 = __ldcg(gac + 105 + k * 21 + 2 * j + 1);
        float m0 = sx0 * invdS;
        float m1 = sx1 * invdS;
        float v0 = (sxx0 - 2.0f * m0 * sx0 + m0 * m0 * S) * invdS + 1e-6f;  // var + EPS_VAR
        float v1 = (sxx1 - 2.0f * m1 * sx1 + m1 * m1 * S) * invdS + 1e-6f;
        float ic0 = 1.0f / (v0 + 1e-6f);
        float ic1 = 1.0f / (v1 + 1e-6f);
        float4 gp;
        gp.x = -0.5f * ic0;
        gp.y = -0.5f * ic1;
        gp.z = ic0 * m0;
        gp.w = ic1 * m1;
        g_params4[(b * Kn + k) * 11 + j] = gp;
        sCp[k][j] = -0.5f * (logf(6.283185307179586f * v0) +
                             logf(6.283185307179586f * v1))
                    - 0.5f * (ic0 * m0 * m0 + ic1 * m1 * m1);
        if (is_last_iter) {
            float2* om = reinterpret_cast<float2*>(out_means + (b * Kn + k) * Fn + 2 * j);
            float2* ov = reinterpret_cast<float2*>(out_var   + (b * Kn + k) * Fn + 2 * j);
            *om = make_float2(m0, m1);
            *ov = make_float2(v0, v1);
        }
    }
    __syncthreads();
    if (tid < Kn) {
        int k = tid;
        float pi = sS[k] / sSum;
        float C = logf(pi);
#pragma unroll
        for (int j = 0; j < 10; j++) C += sCp[k][j];
        float4 t = make_float4(C, 0.0f, 0.0f, 0.0f);
        g_params4[(b * Kn + k) * 11 + 10] = t;
        if (is_last_iter) out_pi[b * Kn + k] = pi;
    }
    __syncthreads();   // reads of g_acc done -> safe to reset
    for (int i = tid; i < 210; i += THR) g_acc[b * 210 + i] = 0.0f;
    __threadfence();   // make resets visible before block exit
}

// ---------------------------------------------------------------- final E-step: write ll + post [B,N,K], staged in/out
__launch_bounds__(TO)
__global__ void estep_out_kernel(const float* __restrict__ data,
                                 float* __restrict__ out_ll,
                                 float* __restrict__ out_post) {
    __shared__ EStepSmem sp;
    __shared__ __align__(16) float sX[TO * Fn];    // 20KB staged input tile
    __shared__ __align__(16) float sLL[TO * Kn];
    __shared__ __align__(16) float sPP[TO * Kn];
    const int tid  = threadIdx.x;
    const int half = tid & 127;            // 128 compute threads process 2 points each
    const int b    = blockIdx.y;
    load_params_smem(&sp, b, tid);

    const int base   = blockIdx.x * TO;
    const int nvalid = min(TO, Nn - base);         // 256 or 128

    // coalesced staging
    {
        const float4* src4 =
            reinterpret_cast<const float4*>(data + ((size_t)b * Nn + base) * Fn);
        float4* sx4 = reinterpret_cast<float4*>(sX);
        const int nf4 = nvalid * (Fn / 4);
        for (int i = tid; i < nf4; i += TO) sx4[i] = __ldg(src4 + i);
    }
    __syncthreads();

    if (tid < 128) {
        if (nvalid == TO) {
            float la[Kn], lb[Kn], pa[Kn], pb[Kn];
            loglik_softmax2(&sp,
                reinterpret_cast<const ulonglong2*>(sX + half * Fn),
                reinterpret_cast<const ulonglong2*>(sX + (half + 128) * Fn),
                la, pa, lb, pb);
#pragma unroll
            for (int k = 0; k < Kn; k++) {
                sLL[half * Kn + k]         = la[k];
                sPP[half * Kn + k]         = pa[k];
                sLL[(half + 128) * Kn + k] = lb[k];
                sPP[(half + 128) * Kn + k] = pb[k];
            }
        } else {
            float l[Kn], p[Kn];
            loglik_softmax1(&sp, reinterpret_cast<const ulonglong2*>(sX + half * Fn), l, p);
#pragma unroll
            for (int k = 0; k < Kn; k++) {
                sLL[half * Kn + k] = l[k];
                sPP[half * Kn + k] = p[k];
            }
        }
    }
    __syncthreads();

    const int nf4 = nvalid * Kn / 4;                 // nvalid*5 always /4 (nvalid 256 or 128)
    const size_t off = ((size_t)b * Nn + base) * Kn; // multiple of 4 floats -> 16B aligned
    float4* dll = reinterpret_cast<float4*>(out_ll + off);
    float4* dpp = reinterpret_cast<float4*>(out_post + off);
    const float4* sll4 = reinterpret_cast<const float4*>(sLL);
    const float4* spp4 = reinterpret_cast<const float4*>(sPP);
    for (int i = tid; i < nf4; i += TO) dll[i] = sll4[i];
    for (int i = tid; i < nf4; i += TO) dpp[i] = spp4[i];
}

// ---------------------------------------------------------------- launch
extern "C" void kernel_launch(void* const* d_in, const int* in_sizes, int n_in,
                              void* d_out, int out_size) {
    const float* data  = (const float*)d_in[0];
    const float* means = (const float*)d_in[1];
    const float* var   = (const float*)d_in[2];
    const float* pri   = (const float*)d_in[3];

    float* out = (float*)d_out;
    size_t NK = (size_t)Bn * Nn * Kn;                 // 3,200,000
    float* out_ll    = out;
    float* out_post  = out + NK;
    float* out_means = out + 2 * NK;
    float* out_var   = out_means + Bn * Kn * Fn;      // +800
    float* out_pi    = out_var   + Bn * Kn * Fn;      // +800

    for (int it = 0; it < NITER; it++) {
        accum_kernel<<<dim3(GRIDX, Bn), THR>>>(data, means, var, pri, it,
                                               out_means, out_var, out_pi);
    }
    estep_out_kernel<<<dim3(NTO, Bn), TO>>>(data, out_ll, out_post);
}

// round 14
// speedup vs baseline: 1.3492x; 1.1116x over previous
#include <cuda_runtime.h>

typedef unsigned long long ull;

// GMM EM on GB300 — single persistent kernel (5 EM iterations + final E-step).
// Cross-block transport: per-iteration atomic sum buffers + tickets (R12-proven pattern)
// and an acquire/release generation flag. Params are recomputed locally by every block.

#define Bn 8
#define Nn 80000
#define Kn 5
#define Fn 20
#define NITER 5
#define THR 128                            // threads per block
#define TILE 256                           // points per tile (2 per thread)
#define NTILES ((Nn + TILE - 1) / TILE)    // 313 (last tile: 128 valid)
#define GRIDX 111                          // 111*8 = 888 blocks = one resident wave (proven in R13 run)

// Per-iteration accumulators: g_acc5[(it*Bn+b)*210 + i]
//   Sx[k][f] at k*21+f (f==20 is the constant-1 feature -> Sx == cluster size S),
//   Sxx[k][f] at 105 + k*21+f.
// Buffer it-1 is reset by iteration it's finalize; buffer NITER-1 by the completion ticket.
__device__ float g_acc5[NITER * Bn * 210];
__device__ int   g_cnt5[(NITER + 1) * Bn]; // tickets per iteration + completion ticket
__device__ int   g_gen[Bn];                // monotonic generation counter (never reset)

// ---------------------------------------------------------------- f32x2 + sync helpers
__device__ __forceinline__ ull pk2(float lo, float hi) {
    ull r; asm("mov.b64 %0,{%1,%2};" : "=l"(r) : "f"(lo), "f"(hi)); return r;
}
__device__ __forceinline__ void up2(ull v, float& lo, float& hi) {
    asm("mov.b64 {%0,%1},%2;" : "=f"(lo), "=f"(hi) : "l"(v));
}
__device__ __forceinline__ ull fma2(ull a, ull b, ull c) {
    ull d; asm("fma.rn.f32x2 %0,%1,%2,%3;" : "=l"(d) : "l"(a), "l"(b), "l"(c)); return d;
}
__device__ __forceinline__ ull mul2(ull a, ull b) {
    ull d; asm("mul.rn.f32x2 %0,%1,%2;" : "=l"(d) : "l"(a), "l"(b)); return d;
}
__device__ __forceinline__ int ld_acquire(const int* p) {
    int v;
    asm volatile("ld.acquire.gpu.global.b32 %0,[%1];" : "=r"(v) : "l"(p) : "memory");
    return v;
}
__device__ __forceinline__ void st_release(int* p, int v) {
    asm volatile("st.release.gpu.global.b32 [%0],%1;" :: "l"(p), "r"(v) : "memory");
}

// ---------------------------------------------------------------- E-step smem params
struct EStepSmem {
    ulonglong2 AB[Kn][10];   // .x = packed(A_{2j},A_{2j+1}), .y = packed(B_{2j},B_{2j+1})
    float      C[Kn];
};

__device__ __forceinline__ void softmax5(const float* l, float* p) {
    float m = l[0];
#pragma unroll
    for (int k = 1; k < Kn; k++) m = fmaxf(m, l[k]);
    float s = 0.0f;
#pragma unroll
    for (int k = 0; k < Kn; k++) { p[k] = __expf(l[k] - m); s += p[k]; }
    float inv = __fdividef(1.0f, s);
#pragma unroll
    for (int k = 0; k < Kn; k++) p[k] *= inv;
}

__device__ __forceinline__ void loglik_softmax1(const EStepSmem* sp,
                                                const ulonglong2* __restrict__ xp,
                                                float* l, float* p) {
    ull acc[Kn] = {0, 0, 0, 0, 0};
#pragma unroll
    for (int jj = 0; jj < 5; jj++) {
        ulonglong2 v = xp[jj];
#pragma unroll
        for (int k = 0; k < Kn; k++) {
            ulonglong2 ab0 = sp->AB[k][2 * jj];
            ulonglong2 ab1 = sp->AB[k][2 * jj + 1];
            acc[k] = fma2(fma2(ab0.x, v.x, ab0.y), v.x, acc[k]);
            acc[k] = fma2(fma2(ab1.x, v.y, ab1.y), v.y, acc[k]);
        }
    }
#pragma unroll
    for (int k = 0; k < Kn; k++) {
        float lo, hi; up2(acc[k], lo, hi);
        l[k] = sp->C[k] + lo + hi;
    }
    softmax5(l, p);
}

__device__ __forceinline__ void loglik_softmax2(const EStepSmem* sp,
                                                const ulonglong2* __restrict__ xa,
                                                const ulonglong2* __restrict__ xb,
                                                float* la, float* pa,
                                                float* lb, float* pb) {
    ull acc0[Kn] = {0, 0, 0, 0, 0};
    ull acc1[Kn] = {0, 0, 0, 0, 0};
#pragma unroll
    for (int jj = 0; jj < 5; jj++) {
        ulonglong2 va = xa[jj];
        ulonglong2 vb = xb[jj];
#pragma unroll
        for (int k = 0; k < Kn; k++) {
            ulonglong2 ab0 = sp->AB[k][2 * jj];       // one LDS.128, two points
            ulonglong2 ab1 = sp->AB[k][2 * jj + 1];
            acc0[k] = fma2(fma2(ab0.x, va.x, ab0.y), va.x, acc0[k]);
            acc0[k] = fma2(fma2(ab1.x, va.y, ab1.y), va.y, acc0[k]);
            acc1[k] = fma2(fma2(ab0.x, vb.x, ab0.y), vb.x, acc1[k]);
            acc1[k] = fma2(fma2(ab1.x, vb.y, ab1.y), vb.y, acc1[k]);
        }
    }
#pragma unroll
    for (int k = 0; k < Kn; k++) {
        float lo, hi;
        up2(acc0[k], lo, hi); la[k] = sp->C[k] + lo + hi;
        up2(acc1[k], lo, hi); lb[k] = sp->C[k] + lo + hi;
    }
    softmax5(la, pa);
    softmax5(lb, pb);
}

// ---------------------------------------------------------------- the persistent kernel
__launch_bounds__(THR, 6)
__global__ void gmm_persistent(const float* __restrict__ data,
                               const float* __restrict__ in_means,
                               const float* __restrict__ in_var,
                               const float* __restrict__ in_pri,
                               float* __restrict__ out_ll,
                               float* __restrict__ out_post,
                               float* __restrict__ out_means,
                               float* __restrict__ out_var,
                               float* __restrict__ out_pi) {
    __shared__ EStepSmem sp;
    __shared__ __align__(16) float sX[TILE * Fn];   // staged tile, point-major, 20KB
    __shared__ __align__(16) union {
        struct { float sP[Kn][TILE]; float sred[4 * 210]; } a;    // accum phases
        struct { float sLL[TILE * Kn]; float sPP[TILE * Kn]; } o; // output phase
    } U;
    __shared__ float sCp[Kn][10];
    __shared__ float sS[Kn];
    __shared__ int   sIsLast;
    __shared__ int   sBase;

    const int tid  = threadIdx.x;
    const int b    = blockIdx.y;
    const int wid  = tid >> 5;
    const int lane = tid & 31;
    const ull ONE2 = pk2(1.0f, 1.0f);
    const float* dbase = data + (size_t)b * Nn * Fn;

    // generation base: read before this block tickets iter 0, so no iter-0 release
    // (which requires all GRIDX tickets) can precede it.
    if (tid == 0) sBase = ld_acquire(&g_gen[b]);

    // ---- iteration-0 params bootstrapped from raw inputs (every block)
    if (tid < 50) {
        int k = tid / 10, j = tid - k * 10;
        const float* mu = in_means + (b * Kn + k) * Fn + 2 * j;
        const float* vv = in_var   + (b * Kn + k) * Fn + 2 * j;
        float v0 = vv[0], v1 = vv[1], m0 = mu[0], m1 = mu[1];
        float ic0 = 1.0f / (v0 + 1e-6f);
        float ic1 = 1.0f / (v1 + 1e-6f);
        sp.AB[k][j].x = pk2(-0.5f * ic0, -0.5f * ic1);
        sp.AB[k][j].y = pk2(ic0 * m0, ic1 * m1);
        sCp[k][j] = -0.5f * (logf(6.283185307179586f * v0) +
                             logf(6.283185307179586f * v1))
                    - 0.5f * (ic0 * m0 * m0 + ic1 * m1 * m1);
    }
    __syncthreads();
    if (tid < Kn) {
        float C = logf(in_pri[b * Kn + tid]);
#pragma unroll
        for (int j = 0; j < 10; j++) C += sCp[tid][j];
        sp.C[tid] = C;
    }

    // ================================================================ EM iterations
    for (int it = 0; it < NITER; it++) {
        ull Sx2[Kn]  = {0, 0, 0, 0, 0};   // f32x2 lane-paired accumulators (lane = feature)
        ull Sxx2[Kn] = {0, 0, 0, 0, 0};

        for (int tile = blockIdx.x; tile < NTILES; tile += GRIDX) {
            const int base   = tile * TILE;
            const int nvalid = min(TILE, Nn - base);   // 256 or 128 (last tile only)

            __syncthreads();   // smem safe to overwrite; orders sp writes before reads

            // phase 0: coalesced staging of tile into smem (float4)
            {
                const float4* src4 = reinterpret_cast<const float4*>(dbase + base * Fn);
                float4* sx4 = reinterpret_cast<float4*>(sX);
                const int nf4 = nvalid * (Fn / 4);     // 1280 or 640
#pragma unroll
                for (int u = 0; u < TILE * (Fn / 4) / THR; u++) {
                    int i = tid + u * THR;
                    if (i < nf4) sx4[i] = __ldg(src4 + i);
                }
            }
            __syncthreads();

            // phase 1: thread handles points tid and tid+128 (x from smem), j-outer
            if (nvalid == TILE) {
                float la[Kn], lb[Kn], pa[Kn], pb[Kn];
                loglik_softmax2(&sp,
                    reinterpret_cast<const ulonglong2*>(sX + tid * Fn),
                    reinterpret_cast<const ulonglong2*>(sX + (tid + THR) * Fn),
                    la, pa, lb, pb);
#pragma unroll
                for (int k = 0; k < Kn; k++) U.a.sP[k][tid]       = pa[k];
#pragma unroll
                for (int k = 0; k < Kn; k++) U.a.sP[k][tid + THR] = pb[k];
            } else {
                float l[Kn], p[Kn];
                loglik_softmax1(&sp, reinterpret_cast<const ulonglong2*>(sX + tid * Fn), l, p);
#pragma unroll
                for (int k = 0; k < Kn; k++) U.a.sP[k][tid] = p[k];
            }
            __syncthreads();

            // phase 2: warp owns 64 points (4 at a time), lane owns feature f
            const int t0w = wid * 64;
            if (t0w < nvalid) {
                const bool act = lane < 20;
                const float* xcol = sX + t0w * Fn + (act ? lane : 0);
#pragma unroll 4
                for (int i = 0; i < 64; i += 4) {
                    float x0 = xcol[(i + 0) * Fn];
                    float x1 = xcol[(i + 1) * Fn];
                    float x2 = xcol[(i + 2) * Fn];
                    float x3 = xcol[(i + 3) * Fn];
                    ull xp01 = act ? pk2(x0, x1) : ONE2;
                    ull xp23 = act ? pk2(x2, x3) : ONE2;
                    ull xx01 = mul2(xp01, xp01);
                    ull xx23 = mul2(xp23, xp23);
#pragma unroll
                    for (int k = 0; k < Kn; k++) {
                        ulonglong2 pp =
                            *reinterpret_cast<const ulonglong2*>(&U.a.sP[k][t0w + i]);
                        Sx2[k]  = fma2(pp.x, xp01, Sx2[k]);
                        Sx2[k]  = fma2(pp.y, xp23, Sx2[k]);
                        Sxx2[k] = fma2(pp.x, xx01, Sxx2[k]);
                        Sxx2[k] = fma2(pp.y, xx23, Sxx2[k]);
                    }
                }
            }
        }

        // -------- block reduction + one atomicAdd per entry into buffer[it]
        float* gacw = &g_acc5[(it * Bn + b) * 210];
        __syncthreads();
        if (lane < 21) {
#pragma unroll
            for (int k = 0; k < Kn; k++) {
                float lo, hi; up2(Sx2[k], lo, hi);
                U.a.sred[wid * 210 + k * 21 + lane] = lo + hi;
            }
#pragma unroll
            for (int k = 0; k < Kn; k++) {
                float lo, hi; up2(Sxx2[k], lo, hi);
                U.a.sred[wid * 210 + 105 + k * 21 + lane] = lo + hi;
            }
        }
        __syncthreads();
        for (int i = tid; i < 210; i += THR) {
            float v = U.a.sred[i] + U.a.sred[210 + i] + U.a.sred[420 + i] + U.a.sred[630 + i];
            atomicAdd(gacw + i, v);
        }

        // -------- ticket (R12-proven pattern): fence -> barrier -> tid0 counts
        __threadfence();
        __syncthreads();
        if (tid == 0)
            sIsLast = (atomicAdd(&g_cnt5[it * Bn + b], 1) == GRIDX - 1) ? 1 : 0;
        __syncthreads();

        const int target = sBase + it + 1;
        if (sIsLast) {
            __threadfence();                           // acquire for observed tickets
            if (tid == 0) st_release(&g_gen[b], target);  // release: sums complete
            // deferred reset of the PREVIOUS iteration's buffer (provably unread now)
            if (it >= 1) {
                for (int i = tid; i < 210; i += THR)
                    g_acc5[((it - 1) * Bn + b) * 210 + i] = 0.0f;
                if (tid == 0) g_cnt5[(it - 1) * Bn + b] = 0;
            }
        } else {
            if (tid == 0) {
                while (ld_acquire(&g_gen[b]) - target < 0) { }
            }
            __syncthreads();   // tid0's acquire happens-before all threads below
        }

        // -------- every block recomputes M-step params locally from buffer[it]
        if (tid < 56) (void)ld_acquire(&g_gen[b]);     // per-reader acquire (belt)
        const float* gac = gacw;
        const int last_it = (it == NITER - 1);
        if (tid < 50) {
            int k = tid / 10, j = tid - k * 10;
            float S = __ldcg(gac + k * 21 + 20);
            float invdS = 1.0f / (S + 1e-7f);
            float sx0  = __ldcg(gac + k * 21 + 2 * j);
            float sx1  = __ldcg(gac + k * 21 + 2 * j + 1);
            float sxx0 = __ldcg(gac + 105 + k * 21 + 2 * j);
            float sxx1 = __ldcg(gac + 105 + k * 21 + 2 * j + 1);
            float m0 = sx0 * invdS;
            float m1 = sx1 * invdS;
            float v0 = (sxx0 - 2.0f * m0 * sx0 + m0 * m0 * S) * invdS + 1e-6f;  // var+EPS
            float v1 = (sxx1 - 2.0f * m1 * sx1 + m1 * m1 * S) * invdS + 1e-6f;
            float ic0 = 1.0f / (v0 + 1e-6f);
            float ic1 = 1.0f / (v1 + 1e-6f);
            sp.AB[k][j].x = pk2(-0.5f * ic0, -0.5f * ic1);
            sp.AB[k][j].y = pk2(ic0 * m0, ic1 * m1);
            sCp[k][j] = -0.5f * (logf(6.283185307179586f * v0) +
                                 logf(6.283185307179586f * v1))
                        - 0.5f * (ic0 * m0 * m0 + ic1 * m1 * m1);
            if (last_it && blockIdx.x == 0) {
                float2* om = reinterpret_cast<float2*>(out_means + (b * Kn + k) * Fn + 2 * j);
                float2* ov = reinterpret_cast<float2*>(out_var   + (b * Kn + k) * Fn + 2 * j);
                *om = make_float2(m0, m1);
                *ov = make_float2(v0, v1);
            }
        }
        if (tid >= 50 && tid < 55) sS[tid - 50] = __ldcg(gac + (tid - 50) * 21 + 20);
        __syncthreads();
        if (tid < Kn) {
            float sum = sS[0] + sS[1] + sS[2] + sS[3] + sS[4];
            float pi = sS[tid] / fmaxf(sum, (float)Nn * 1e-12f);
            float C = logf(pi);
#pragma unroll
            for (int j = 0; j < 10; j++) C += sCp[tid][j];
            sp.C[tid] = C;
            if (last_it && blockIdx.x == 0) out_pi[b * Kn + tid] = pi;
        }
        // next tile-loop's top __syncthreads orders sp writes before reads
    }

    // ================================================================ final E-step
    for (int tile = blockIdx.x; tile < NTILES; tile += GRIDX) {
        const int base   = tile * TILE;
        const int nvalid = min(TILE, Nn - base);   // 256 or 128

        __syncthreads();
        {
            const float4* src4 = reinterpret_cast<const float4*>(dbase + base * Fn);
            float4* sx4 = reinterpret_cast<float4*>(sX);
            const int nf4 = nvalid * (Fn / 4);
#pragma unroll
            for (int u = 0; u < TILE * (Fn / 4) / THR; u++) {
                int i = tid + u * THR;
                if (i < nf4) sx4[i] = __ldg(src4 + i);
            }
        }
        __syncthreads();

        if (nvalid == TILE) {
            float la[Kn], lb[Kn], pa[Kn], pb[Kn];
            loglik_softmax2(&sp,
                reinterpret_cast<const ulonglong2*>(sX + tid * Fn),
                reinterpret_cast<const ulonglong2*>(sX + (tid + THR) * Fn),
                la, pa, lb, pb);
#pragma unroll
            for (int k = 0; k < Kn; k++) {
                U.o.sLL[tid * Kn + k]         = la[k];
                U.o.sPP[tid * Kn + k]         = pa[k];
                U.o.sLL[(tid + THR) * Kn + k] = lb[k];
                U.o.sPP[(tid + THR) * Kn + k] = pb[k];
            }
        } else {
            float l[Kn], p[Kn];
            loglik_softmax1(&sp, reinterpret_cast<const ulonglong2*>(sX + tid * Fn), l, p);
#pragma unroll
            for (int k = 0; k < Kn; k++) {
                U.o.sLL[tid * Kn + k] = l[k];
                U.o.sPP[tid * Kn + k] = p[k];
            }
        }
        __syncthreads();

        const int nf4 = nvalid * Kn / 4;                 // nvalid*5 always /4
        const size_t off = ((size_t)b * Nn + base) * Kn; // 16B aligned
        float4* dll = reinterpret_cast<float4*>(out_ll + off);
        float4* dpp = reinterpret_cast<float4*>(out_post + off);
        const float4* sll4 = reinterpret_cast<const float4*>(U.o.sLL);
        const float4* spp4 = reinterpret_cast<const float4*>(U.o.sPP);
        for (int i = tid; i < nf4; i += THR) dll[i] = sll4[i];
        for (int i = tid; i < nf4; i += THR) dpp[i] = spp4[i];
    }

    // -------- completion ticket: last block per b resets buffer[NITER-1] + counters
    __threadfence();
    __syncthreads();
    if (tid == 0)
        sIsLast = (atomicAdd(&g_cnt5[NITER * Bn + b], 1) == GRIDX - 1) ? 1 : 0;
    __syncthreads();
    if (sIsLast) {
        for (int i = tid; i < 210; i += THR)
            g_acc5[((NITER - 1) * Bn + b) * 210 + i] = 0.0f;
        if (tid == 0) {
            g_cnt5[(NITER - 1) * Bn + b] = 0;
            g_cnt5[NITER * Bn + b] = 0;
        }
        // g_gen stays monotonic by design (sBase snapshot handles replays)
    }
}

// ---------------------------------------------------------------- launch
extern "C" void kernel_launch(void* const* d_in, const int* in_sizes, int n_in,
                              void* d_out, int out_size) {
    const float* data  = (const float*)d_in[0];
    const float* means = (const float*)d_in[1];
    const float* var   = (const float*)d_in[2];
    const float* pri   = (const float*)d_in[3];

    float* out = (float*)d_out;
    size_t NK = (size_t)Bn * Nn * Kn;                 // 3,200,000
    float* out_ll    = out;
    float* out_post  = out + NK;
    float* out_means = out + 2 * NK;
    float* out_var   = out_means + Bn * Kn * Fn;      // +800
    float* out_pi    = out_var   + Bn * Kn * Fn;      // +800

    gmm_persistent<<<dim3(GRIDX, Bn), THR>>>(data, means, var, pri,
                                             out_ll, out_post,
                                             out_means, out_var, out_pi);
}

// round 17
// speedup vs baseline: 1.3621x; 1.0096x over previous
#include <cuda_runtime.h>

typedef unsigned long long ull;

// GMM EM on GB300 — single persistent kernel, warp-autonomous tiles.
// Cross-block transport: per-iteration atomic sum buffers + tickets + acquire/release
// generation flag (R14-proven). Params recomputed locally by every block.

#define Bn 8
#define Nn 80000
#define Kn 5
#define Fn 20
#define NITER 5
#define THR 128                            // threads per block (4 warps)
#define TILE 256                           // points per tile (64 per warp)
#define NTILES ((Nn + TILE - 1) / TILE)    // 313 (last tile: 128 valid = 2 warps)
#define GRIDX 111                          // 111*8 = 888 blocks = one resident wave

// Per-iteration accumulators: g_acc5[(it*Bn+b)*210 + i]
//   Sx[k][f] at k*21+f (f==20 is the constant-1 feature -> Sx == cluster size S),
//   Sxx[k][f] at 105 + k*21+f.
__device__ float g_acc5[NITER * Bn * 210];
__device__ int   g_cnt5[(NITER + 1) * Bn]; // tickets per iteration + completion ticket
__device__ int   g_gen[Bn];                // monotonic generation counter (never reset)

// ---------------------------------------------------------------- f32x2 + sync helpers
__device__ __forceinline__ ull pk2(float lo, float hi) {
    ull r; asm("mov.b64 %0,{%1,%2};" : "=l"(r) : "f"(lo), "f"(hi)); return r;
}
__device__ __forceinline__ void up2(ull v, float& lo, float& hi) {
    asm("mov.b64 {%0,%1},%2;" : "=f"(lo), "=f"(hi) : "l"(v));
}
__device__ __forceinline__ ull fma2(ull a, ull b, ull c) {
    ull d; asm("fma.rn.f32x2 %0,%1,%2,%3;" : "=l"(d) : "l"(a), "l"(b), "l"(c)); return d;
}
__device__ __forceinline__ ull mul2(ull a, ull b) {
    ull d; asm("mul.rn.f32x2 %0,%1,%2;" : "=l"(d) : "l"(a), "l"(b)); return d;
}
__device__ __forceinline__ int ld_acquire(const int* p) {
    int v;
    asm volatile("ld.acquire.gpu.global.b32 %0,[%1];" : "=r"(v) : "l"(p) : "memory");
    return v;
}
__device__ __forceinline__ void st_release(int* p, int v) {
    asm volatile("st.release.gpu.global.b32 [%0],%1;" :: "l"(p), "r"(v) : "memory");
}

// ---------------------------------------------------------------- E-step smem params
struct EStepSmem {
    ulonglong2 AB[Kn][10];   // .x = packed(A_{2j},A_{2j+1}), .y = packed(B_{2j},B_{2j+1})
    float      C[Kn];
};

__device__ __forceinline__ void softmax5(const float* l, float* p) {
    float m = l[0];
#pragma unroll
    for (int k = 1; k < Kn; k++) m = fmaxf(m, l[k]);
    float s = 0.0f;
#pragma unroll
    for (int k = 0; k < Kn; k++) { p[k] = __expf(l[k] - m); s += p[k]; }
    float inv = __fdividef(1.0f, s);
#pragma unroll
    for (int k = 0; k < Kn; k++) p[k] *= inv;
}

// two-point log-lik + softmax sharing param loads (j-outer)
__device__ __forceinline__ void loglik_softmax2(const EStepSmem* sp,
                                                const ulonglong2* __restrict__ xa,
                                                const ulonglong2* __restrict__ xb,
                                                float* la, float* pa,
                                                float* lb, float* pb) {
    ull acc0[Kn] = {0, 0, 0, 0, 0};
    ull acc1[Kn] = {0, 0, 0, 0, 0};
#pragma unroll
    for (int jj = 0; jj < 5; jj++) {
        ulonglong2 va = xa[jj];
        ulonglong2 vb = xb[jj];
#pragma unroll
        for (int k = 0; k < Kn; k++) {
            ulonglong2 ab0 = sp->AB[k][2 * jj];       // one LDS.128, two points
            ulonglong2 ab1 = sp->AB[k][2 * jj + 1];
            acc0[k] = fma2(fma2(ab0.x, va.x, ab0.y), va.x, acc0[k]);
            acc0[k] = fma2(fma2(ab1.x, va.y, ab1.y), va.y, acc0[k]);
            acc1[k] = fma2(fma2(ab0.x, vb.x, ab0.y), vb.x, acc1[k]);
            acc1[k] = fma2(fma2(ab1.x, vb.y, ab1.y), vb.y, acc1[k]);
        }
    }
#pragma unroll
    for (int k = 0; k < Kn; k++) {
        float lo, hi;
        up2(acc0[k], lo, hi); la[k] = sp->C[k] + lo + hi;
        up2(acc1[k], lo, hi); lb[k] = sp->C[k] + lo + hi;
    }
    softmax5(la, pa);
    softmax5(lb, pb);
}

// ---------------------------------------------------------------- the persistent kernel
__launch_bounds__(THR, 6)
__global__ void gmm_persistent(const float* __restrict__ data,
                               const float* __restrict__ in_means,
                               const float* __restrict__ in_var,
                               const float* __restrict__ in_pri,
                               float* __restrict__ out_ll,
                               float* __restrict__ out_post,
                               float* __restrict__ out_means,
                               float* __restrict__ out_var,
                               float* __restrict__ out_pi) {
    __shared__ EStepSmem sp;
    __shared__ __align__(16) float sX[TILE * Fn];   // staged tile, point-major, warp-sliced
    __shared__ __align__(16) union {
        struct { float sP[Kn][TILE]; float sred[4 * 210]; } a;    // accum phases
        struct { float sLL[TILE * Kn]; float sPP[TILE * Kn]; } o; // output phase
    } U;
    __shared__ float sCp[Kn][10];
    __shared__ float sS[Kn];
    __shared__ int   sIsLast;
    __shared__ int   sBase;

    const int tid  = threadIdx.x;
    const int b    = blockIdx.y;
    const int wid  = tid >> 5;
    const int lane = tid & 31;
    const int t0   = wid * 64;            // this warp's slice within the tile
    const ull ONE2 = pk2(1.0f, 1.0f);
    const float* dbase = data + (size_t)b * Nn * Fn;

    // generation base: read before this block tickets iter 0
    if (tid == 0) sBase = ld_acquire(&g_gen[b]);

    // ---- iteration-0 params bootstrapped from raw inputs (every block)
    if (tid < 50) {
        int k = tid / 10, j = tid - k * 10;
        const float* mu = in_means + (b * Kn + k) * Fn + 2 * j;
        const float* vv = in_var   + (b * Kn + k) * Fn + 2 * j;
        float v0 = vv[0], v1 = vv[1], m0 = mu[0], m1 = mu[1];
        float ic0 = 1.0f / (v0 + 1e-6f);
        float ic1 = 1.0f / (v1 + 1e-6f);
        sp.AB[k][j].x = pk2(-0.5f * ic0, -0.5f * ic1);
        sp.AB[k][j].y = pk2(ic0 * m0, ic1 * m1);
        sCp[k][j] = -0.5f * (logf(6.283185307179586f * v0) +
                             logf(6.283185307179586f * v1))
                    - 0.5f * (ic0 * m0 * m0 + ic1 * m1 * m1);
    }
    __syncthreads();
    if (tid < Kn) {
        float C = logf(in_pri[b * Kn + tid]);
#pragma unroll
        for (int j = 0; j < 10; j++) C += sCp[tid][j];
        sp.C[tid] = C;
    }

    // ================================================================ EM iterations
    for (int it = 0; it < NITER; it++) {
        ull Sx2[Kn]  = {0, 0, 0, 0, 0};   // f32x2 lane-paired accumulators (lane = feature)
        ull Sxx2[Kn] = {0, 0, 0, 0, 0};

        __syncthreads();   // sp writes (bootstrap / recompute) visible to all warps

        for (int tile = blockIdx.x; tile < NTILES; tile += GRIDX) {
            const int base   = tile * TILE;
            const int nvalid = min(TILE, Nn - base);   // 256 or 128, both multiples of 64
            if (t0 >= nvalid) continue;                // warp-autonomous: no block barriers

            // -------- stage this warp's 64 points (coalesced float4)
            {
                const float4* src4 =
                    reinterpret_cast<const float4*>(dbase + (size_t)(base + t0) * Fn);
                float4* sx4 = reinterpret_cast<float4*>(sX + t0 * Fn);
#pragma unroll
                for (int u = 0; u < 10; u++)           // 64*20/4 = 320 float4
                    sx4[lane + 32 * u] = __ldg(src4 + lane + 32 * u);
            }
            __syncwarp();

            // -------- phase 1: lane handles points t0+lane and t0+lane+32, j-outer
            {
                float la[Kn], lb[Kn], pa[Kn], pb[Kn];
                loglik_softmax2(&sp,
                    reinterpret_cast<const ulonglong2*>(sX + (t0 + lane) * Fn),
                    reinterpret_cast<const ulonglong2*>(sX + (t0 + lane + 32) * Fn),
                    la, pa, lb, pb);
#pragma unroll
                for (int k = 0; k < Kn; k++) U.a.sP[k][t0 + lane]      = pa[k];
#pragma unroll
                for (int k = 0; k < Kn; k++) U.a.sP[k][t0 + lane + 32] = pb[k];
            }
            __syncwarp();

            // -------- phase 2: warp accumulates its own 64 points (4 at a time), lane = feature
            {
                const bool act = lane < 20;
                const float* xcol = sX + t0 * Fn + (act ? lane : 0);
#pragma unroll 4
                for (int i = 0; i < 64; i += 4) {
                    float x0 = xcol[(i + 0) * Fn];
                    float x1 = xcol[(i + 1) * Fn];
                    float x2 = xcol[(i + 2) * Fn];
                    float x3 = xcol[(i + 3) * Fn];
                    ull xp01 = act ? pk2(x0, x1) : ONE2;
                    ull xp23 = act ? pk2(x2, x3) : ONE2;
                    ull xx01 = mul2(xp01, xp01);
                    ull xx23 = mul2(xp23, xp23);
#pragma unroll
                    for (int k = 0; k < Kn; k++) {
                        ulonglong2 pp =
                            *reinterpret_cast<const ulonglong2*>(&U.a.sP[k][t0 + i]);
                        Sx2[k]  = fma2(pp.x, xp01, Sx2[k]);
                        Sx2[k]  = fma2(pp.y, xp23, Sx2[k]);
                        Sxx2[k] = fma2(pp.x, xx01, Sxx2[k]);
                        Sxx2[k] = fma2(pp.y, xx23, Sxx2[k]);
                    }
                }
            }
            __syncwarp();   // sP/sX reusable next tile (warp-private)
        }

        // -------- block reduction + one atomicAdd per entry into buffer[it]
        float* gacw = &g_acc5[(it * Bn + b) * 210];
        __syncthreads();
        if (lane < 21) {   // lane 20 carries the Sigma-p (ones-feature) column
#pragma unroll
            for (int k = 0; k < Kn; k++) {
                float lo, hi; up2(Sx2[k], lo, hi);
                U.a.sred[wid * 210 + k * 21 + lane] = lo + hi;
            }
#pragma unroll
            for (int k = 0; k < Kn; k++) {
                float lo, hi; up2(Sxx2[k], lo, hi);
                U.a.sred[wid * 210 + 105 + k * 21 + lane] = lo + hi;
            }
        }
        __syncthreads();
        for (int i = tid; i < 210; i += THR) {
            float v = U.a.sred[i] + U.a.sred[210 + i] + U.a.sred[420 + i] + U.a.sred[630 + i];
            atomicAdd(gacw + i, v);
        }

        // -------- ticket: fence -> barrier -> tid0 counts (R12/R14-proven)
        __threadfence();
        __syncthreads();
        if (tid == 0)
            sIsLast = (atomicAdd(&g_cnt5[it * Bn + b], 1) == GRIDX - 1) ? 1 : 0;
        __syncthreads();

        const int target = sBase + it + 1;
        if (sIsLast) {
            __threadfence();
            if (tid == 0) st_release(&g_gen[b], target);  // release: sums complete
            if (it >= 1) {   // deferred reset of previous iteration's buffer
                for (int i = tid; i < 210; i += THR)
                    g_acc5[((it - 1) * Bn + b) * 210 + i] = 0.0f;
                if (tid == 0) g_cnt5[(it - 1) * Bn + b] = 0;
            }
        } else {
            if (tid == 0) {
                while (ld_acquire(&g_gen[b]) - target < 0) { }
            }
            __syncthreads();   // tid0's acquire happens-before all threads below
        }

        // -------- every block recomputes M-step params locally from buffer[it]
        if (tid < 56) (void)ld_acquire(&g_gen[b]);     // per-reader acquire (belt)
        const float* gac = gacw;
        const int last_it = (it == NITER - 1);
        if (tid < 50) {
            int k = tid / 10, j = tid - k * 10;
            float S = __ldcg(gac + k * 21 + 20);
            float invdS = 1.0f / (S + 1e-7f);
            float sx0  = __ldcg(gac + k * 21 + 2 * j);
            float sx1  = __ldcg(gac + k * 21 + 2 * j + 1);
            float sxx0 = __ldcg(gac + 105 + k * 21 + 2 * j);
            float sxx1 = __ldcg(gac + 105 + k * 21 + 2 * j + 1);
            float m0 = sx0 * invdS;
            float m1 = sx1 * invdS;
            float v0 = (sxx0 - 2.0f * m0 * sx0 + m0 * m0 * S) * invdS + 1e-6f;  // var+EPS
            float v1 = (sxx1 - 2.0f * m1 * sx1 + m1 * m1 * S) * invdS + 1e-6f;
            float ic0 = 1.0f / (v0 + 1e-6f);
            float ic1 = 1.0f / (v1 + 1e-6f);
            sp.AB[k][j].x = pk2(-0.5f * ic0, -0.5f * ic1);
            sp.AB[k][j].y = pk2(ic0 * m0, ic1 * m1);
            sCp[k][j] = -0.5f * (logf(6.283185307179586f * v0) +
                                 logf(6.283185307179586f * v1))
                        - 0.5f * (ic0 * m0 * m0 + ic1 * m1 * m1);
            if (last_it && blockIdx.x == 0) {
                float2* om = reinterpret_cast<float2*>(out_means + (b * Kn + k) * Fn + 2 * j);
                float2* ov = reinterpret_cast<float2*>(out_var   + (b * Kn + k) * Fn + 2 * j);
                *om = make_float2(m0, m1);
                *ov = make_float2(v0, v1);
            }
        }
        if (tid >= 50 && tid < 55) sS[tid - 50] = __ldcg(gac + (tid - 50) * 21 + 20);
        __syncthreads();
        if (tid < Kn) {
            float sum = sS[0] + sS[1] + sS[2] + sS[3] + sS[4];
            float pi = sS[tid] / fmaxf(sum, (float)Nn * 1e-12f);
            float C = logf(pi);
#pragma unroll
            for (int j = 0; j < 10; j++) C += sCp[tid][j];
            sp.C[tid] = C;
            if (last_it && blockIdx.x == 0) out_pi[b * Kn + tid] = pi;
        }
        // top-of-next-pass __syncthreads orders sp writes before reads
    }

    // ================================================================ final E-step (warp-autonomous)
    __syncthreads();   // final params visible
    for (int tile = blockIdx.x; tile < NTILES; tile += GRIDX) {
        const int base   = tile * TILE;
        const int nvalid = min(TILE, Nn - base);
        if (t0 >= nvalid) continue;

        {
            const float4* src4 =
                reinterpret_cast<const float4*>(dbase + (size_t)(base + t0) * Fn);
            float4* sx4 = reinterpret_cast<float4*>(sX + t0 * Fn);
#pragma unroll
            for (int u = 0; u < 10; u++)               // 64*20/4 = 320 float4
                sx4[lane + 32 * u] = __ldg(src4 + lane + 32 * u);
        }
        __syncwarp();

        {
            float la[Kn], lb[Kn], pa[Kn], pb[Kn];
            loglik_softmax2(&sp,
                reinterpret_cast<const ulonglong2*>(sX + (t0 + lane) * Fn),
                reinterpret_cast<const ulonglong2*>(sX + (t0 + lane + 32) * Fn),
                la, pa, lb, pb);
#pragma unroll
            for (int k = 0; k < Kn; k++) {
                U.o.sLL[(t0 + lane) * Kn + k]      = la[k];
                U.o.sPP[(t0 + lane) * Kn + k]      = pa[k];
                U.o.sLL[(t0 + lane + 32) * Kn + k] = lb[k];
                U.o.sPP[(t0 + lane + 32) * Kn + k] = pb[k];
            }
        }
        __syncwarp();

        // write this warp's 64 pts * 5 floats = 320 floats = 80 float4 per array
        const size_t off = ((size_t)b * Nn + base + t0) * Kn;   // multiple of 320 -> 16B aligned
        float4* dll = reinterpret_cast<float4*>(out_ll + off);
        float4* dpp = reinterpret_cast<float4*>(out_post + off);
        const float4* sll4 = reinterpret_cast<const float4*>(U.o.sLL + t0 * Kn);
        const float4* spp4 = reinterpret_cast<const float4*>(U.o.sPP + t0 * Kn);
#pragma unroll
        for (int i = lane; i < 80; i += 32) dll[i] = sll4[i];
#pragma unroll
        for (int i = lane; i < 80; i += 32) dpp[i] = spp4[i];
        __syncwarp();
    }

    // -------- completion ticket: last block per b resets buffer[NITER-1] + counters
    __threadfence();
    __syncthreads();
    if (tid == 0)
        sIsLast = (atomicAdd(&g_cnt5[NITER * Bn + b], 1) == GRIDX - 1) ? 1 : 0;
    __syncthreads();
    if (sIsLast) {
        for (int i = tid; i < 210; i += THR)
            g_acc5[((NITER - 1) * Bn + b) * 210 + i] = 0.0f;
        if (tid == 0) {
            g_cnt5[(NITER - 1) * Bn + b] = 0;
            g_cnt5[NITER * Bn + b] = 0;
        }
        // g_gen stays monotonic (sBase snapshot handles graph replays)
    }
}

// ---------------------------------------------------------------- launch
extern "C" void kernel_launch(void* const* d_in, const int* in_sizes, int n_in,
                              void* d_out, int out_size) {
    const float* data  = (const float*)d_in[0];
    const float* means = (const float*)d_in[1];
    const float* var   = (const float*)d_in[2];
    const float* pri   = (const float*)d_in[3];

    float* out = (float*)d_out;
    size_t NK = (size_t)Bn * Nn * Kn;                 // 3,200,000
    float* out_ll    = out;
    float* out_post  = out + NK;
    float* out_means = out + 2 * NK;
    float* out_var   = out_means + Bn * Kn * Fn;      // +800
    float* out_pi    = out_var   + Bn * Kn * Fn;      // +800

    gmm_persistent<<<dim3(GRIDX, Bn), THR>>>(data, means, var, pri,
                                             out_ll, out_post,
                                             out_means, out_var, out_pi);
}